// round 1
// baseline (speedup 1.0000x reference)
#include <cuda_runtime.h>

namespace {

constexpr int H     = 26;    // neighbors per query
constexpr int PADH  = 28;    // padded neighbor count for generator linear
constexpr int KP    = 10;    // kernel points
constexpr int CIN   = 64;
constexpr int COUT  = 128;
constexpr int KDIM  = KP * CIN;   // 640
constexpr int TILE  = 32;         // query points per block
constexpr int NT    = 256;        // threads per block (8 warps)
constexpr float INV_EXT = 1.0f / 1.2f;

struct Smem {
  float genWT[84 * 32];        // gen_W transposed: [m][j], j<30 (conflict-free reads)
  float genB[32];
  float sW[TILE][KDIM];        // weighted features per point (phase-1 output)
  float sP[8][84];             // per-warp padded neighbor vector (incl. -1 pads)
  float sKP[8][32];            // per-warp kernel points (30 used)
  float swv[8][KP * H];        // per-warp influence weights w[k*H+h]
  int   sIdx[8][H];            // per-warp neighbor indices
};

__global__ void __launch_bounds__(NT, 2)
kpconv_kernel(const float* __restrict__ q_pts,
              const float* __restrict__ s_pts,
              const float* __restrict__ x,
              const float* __restrict__ genW,
              const float* __restrict__ genB,
              const float* __restrict__ weights,
              const int*   __restrict__ inds,
              float*       __restrict__ out,
              int N, int Ns)
{
  extern __shared__ char smraw[];
  Smem& sm = *reinterpret_cast<Smem*>(smraw);
  const int tid  = threadIdx.x;
  const int lane = tid & 31;
  const int wid  = tid >> 5;

  // Stage gen_W transposed + gen_b into shared (once per block).
  for (int t = tid; t < 30 * 84; t += NT) {
    const int j = t / 84;
    const int m = t - j * 84;
    sm.genWT[m * 32 + j] = genW[t];
  }
  if (tid < 30) sm.genB[tid] = genB[tid];
  __syncthreads();

  const int n_base = blockIdx.x * TILE;

  // ---------------- Phase 1: per-point weighted features ----------------
  // Each warp processes 4 points sequentially.
  for (int it = 0; it < TILE / 8; ++it) {
    const int p = wid * (TILE / 8) + it;
    const int n = n_base + p;
    if (n < N) {
      const float qx = q_pts[3 * n + 0];
      const float qy = q_pts[3 * n + 1];
      const float qz = q_pts[3 * n + 2];

      // Step 1: gather neighbor coordinates, build padded 84-vector.
      if (lane < H) {
        int j = inds[(size_t)n * H + lane];
        float sx, sy, sz;
        if (j >= 0 && j < Ns) {
          sx = s_pts[3 * j + 0];
          sy = s_pts[3 * j + 1];
          sz = s_pts[3 * j + 2];
        } else {
          // shadow support point: far away -> influence 0; clamp index for safe gather
          sx = sy = sz = 1e6f;
          j = 0;
        }
        sm.sP[wid][lane * 3 + 0] = sx - qx;
        sm.sP[wid][lane * 3 + 1] = sy - qy;
        sm.sP[wid][lane * 3 + 2] = sz - qz;
        sm.sIdx[wid][lane] = j;
      } else if (lane < PADH) {
        const int b = lane - H;            // 0 or 1
        sm.sP[wid][78 + b * 3 + 0] = -1.0f;
        sm.sP[wid][78 + b * 3 + 1] = -1.0f;
        sm.sP[wid][78 + b * 3 + 2] = -1.0f;
      }
      __syncwarp();

      // Step 2: generative kernel points kp[30] = gen_W @ p + gen_b.
      if (lane < 30) {
        float acc = sm.genB[lane];
        #pragma unroll
        for (int m = 0; m < 84; ++m)
          acc = fmaf(sm.genWT[m * 32 + lane], sm.sP[wid][m], acc);
        sm.sKP[wid][lane] = acc;
      }
      __syncwarp();

      // Step 3: influence weights w[k][h] = relu(1 - ||nbr_h - kp_k|| / 1.2).
      for (int t = lane; t < KP * H; t += 32) {
        const int k = t / H;
        const int h = t - k * H;
        const float dx = sm.sP[wid][h * 3 + 0] - sm.sKP[wid][k * 3 + 0];
        const float dy = sm.sP[wid][h * 3 + 1] - sm.sKP[wid][k * 3 + 1];
        const float dz = sm.sP[wid][h * 3 + 2] - sm.sKP[wid][k * 3 + 2];
        const float d  = sqrtf(fmaf(dx, dx, fmaf(dy, dy, dz * dz)));
        sm.swv[wid][t] = fmaxf(1.0f - d * INV_EXT, 0.0f);
      }
      __syncwarp();

      // Step 4: weighted[k][i] = sum_h w[k][h] * x[idx[h]][i].
      // Lane owns Cin columns {2*lane, 2*lane+1} for all 10 k.
      float2 acc[KP];
      #pragma unroll
      for (int k = 0; k < KP; ++k) acc[k] = make_float2(0.f, 0.f);

      #pragma unroll 2
      for (int h = 0; h < H; ++h) {
        const int jn = sm.sIdx[wid][h];
        const float2 xv =
            *reinterpret_cast<const float2*>(x + (size_t)jn * CIN + 2 * lane);
        #pragma unroll
        for (int k = 0; k < KP; ++k) {
          const float wv = sm.swv[wid][k * H + h];
          acc[k].x = fmaf(wv, xv.x, acc[k].x);
          acc[k].y = fmaf(wv, xv.y, acc[k].y);
        }
      }
      #pragma unroll
      for (int k = 0; k < KP; ++k)
        *reinterpret_cast<float2*>(&sm.sW[p][k * CIN + 2 * lane]) = acc[k];
    }
    __syncwarp();  // protect per-warp scratch reuse across iterations
  }
  __syncthreads();

  // ---------------- Phase 2: out[32,128] = sW[32,640] @ Wflat[640,128] ----------------
  // Thread (wid, lane): 4 points (wid*4..+3) x 4 output cols (lane*4..+3).
  const int p0 = wid * 4;
  float accO[4][4];
  #pragma unroll
  for (int i = 0; i < 4; ++i)
    #pragma unroll
    for (int j = 0; j < 4; ++j) accO[i][j] = 0.f;

  const float4* __restrict__ Wv = reinterpret_cast<const float4*>(weights);

  #pragma unroll 4
  for (int kk = 0; kk < KDIM; ++kk) {
    const float4 b = Wv[(size_t)kk * (COUT / 4) + lane];
    float a[4];
    #pragma unroll
    for (int pi = 0; pi < 4; ++pi) a[pi] = sm.sW[p0 + pi][kk];
    #pragma unroll
    for (int pi = 0; pi < 4; ++pi) {
      accO[pi][0] = fmaf(a[pi], b.x, accO[pi][0]);
      accO[pi][1] = fmaf(a[pi], b.y, accO[pi][1]);
      accO[pi][2] = fmaf(a[pi], b.z, accO[pi][2]);
      accO[pi][3] = fmaf(a[pi], b.w, accO[pi][3]);
    }
  }

  #pragma unroll
  for (int pi = 0; pi < 4; ++pi) {
    const int n = n_base + p0 + pi;
    if (n < N) {
      float4 o;
      o.x = accO[pi][0];
      o.y = accO[pi][1];
      o.z = accO[pi][2];
      o.w = accO[pi][3];
      *reinterpret_cast<float4*>(out + (size_t)n * COUT + lane * 4) = o;
    }
  }
}

}  // namespace

extern "C" void kernel_launch(void* const* d_in, const int* in_sizes, int n_in,
                              void* d_out, int out_size) {
  const float* q_pts = (const float*)d_in[0];
  const float* s_pts = (const float*)d_in[1];
  const float* x     = (const float*)d_in[2];
  const float* genW  = (const float*)d_in[3];
  const float* genB  = (const float*)d_in[4];
  const float* wts   = (const float*)d_in[5];
  const int*   inds  = (const int*)d_in[6];
  float* out = (float*)d_out;

  const int N  = in_sizes[0] / 3;
  const int Ns = in_sizes[1] / 3;

  cudaFuncSetAttribute(kpconv_kernel,
                       cudaFuncAttributeMaxDynamicSharedMemorySize,
                       (int)sizeof(Smem));

  const int grid = (N + TILE - 1) / TILE;
  kpconv_kernel<<<grid, NT, sizeof(Smem)>>>(q_pts, s_pts, x, genW, genB, wts,
                                            inds, out, N, Ns);
}

// round 3
// speedup vs baseline: 1.7651x; 1.7651x over previous
#include <cuda_runtime.h>
#include <cuda_bf16.h>
#include <cstdint>

// ─────────────────────────────────────────────────────────────────────────────
// KPConv: producer writes weighted features as bf16 hi/lo split pair;
// mma.sync (HMMA) GEMM with 3-way split product computes out = weighted @ W
// with fp32-class accuracy. (tcgen05 is unavailable: harness targets sm_103,
// not sm_103a — verified by round-2 ptxas errors.)
// ─────────────────────────────────────────────────────────────────────────────

namespace {

constexpr int H    = 26;
constexpr int PADH = 28;
constexpr int KP   = 10;
constexpr int CIN  = 64;
constexpr int COUT = 128;
constexpr int KDIM = KP * CIN;   // 640
constexpr int TILE = 32;
constexpr int NT   = 256;
constexpr float INV_EXT = 1.0f / 1.2f;
constexpr int MAXN = 65536;

// Scratch (device-global: no allocation allowed in kernel_launch).
__device__ __nv_bfloat16 g_Ahi[(size_t)MAXN * KDIM];
__device__ __nv_bfloat16 g_Alo[(size_t)MAXN * KDIM];
__device__ __nv_bfloat16 g_Bhi[(size_t)COUT * KDIM];   // [o][k*64+i]
__device__ __nv_bfloat16 g_Blo[(size_t)COUT * KDIM];

__device__ __forceinline__ uint32_t smem_u32(const void* p) {
  uint32_t a;
  asm("{ .reg .u64 t; cvta.to.shared.u64 t, %1; cvt.u32.u64 %0, t; }"
      : "=r"(a) : "l"(p));
  return a;
}

// ───────────────────── Kernel 1: weighted-feature producer ─────────────────────

struct P1Smem {
  float genWT[84 * 32];
  float genB[32];
  float sP[8][84];
  float sKP[8][32];
  float swv[8][H * 12];   // [h][k], stride 12 floats for aligned vector reads
  int   sIdx[8][H];
};

__global__ void __launch_bounds__(NT, 3)
producer_kernel(const float* __restrict__ q_pts,
                const float* __restrict__ s_pts,
                const float* __restrict__ x,
                const float* __restrict__ genW,
                const float* __restrict__ genB,
                const int*   __restrict__ inds,
                int N, int Ns)
{
  __shared__ P1Smem sm;
  const int tid  = threadIdx.x;
  const int lane = tid & 31;
  const int wid  = tid >> 5;

  for (int t = tid; t < 30 * 84; t += NT) {
    const int j = t / 84;
    const int m = t - j * 84;
    sm.genWT[m * 32 + j] = genW[t];
  }
  if (tid < 30) sm.genB[tid] = genB[tid];
  __syncthreads();

  const int n_base = blockIdx.x * TILE;

  for (int it = 0; it < TILE / 8; ++it) {
    const int p = wid * (TILE / 8) + it;
    const int n = n_base + p;
    if (n < N) {
      const float qx = q_pts[3 * n + 0];
      const float qy = q_pts[3 * n + 1];
      const float qz = q_pts[3 * n + 2];

      if (lane < H) {
        int j = inds[(size_t)n * H + lane];
        float sx, sy, sz;
        if (j >= 0 && j < Ns) {
          sx = s_pts[3 * j + 0];
          sy = s_pts[3 * j + 1];
          sz = s_pts[3 * j + 2];
        } else {
          sx = sy = sz = 1e6f;   // shadow point -> zero influence
          j = 0;
        }
        sm.sP[wid][lane * 3 + 0] = sx - qx;
        sm.sP[wid][lane * 3 + 1] = sy - qy;
        sm.sP[wid][lane * 3 + 2] = sz - qz;
        sm.sIdx[wid][lane] = j;
      } else if (lane < PADH) {
        const int b = lane - H;
        sm.sP[wid][78 + b * 3 + 0] = -1.0f;
        sm.sP[wid][78 + b * 3 + 1] = -1.0f;
        sm.sP[wid][78 + b * 3 + 2] = -1.0f;
      }
      __syncwarp();

      if (lane < 30) {
        float acc = sm.genB[lane];
        #pragma unroll
        for (int m = 0; m < 84; ++m)
          acc = fmaf(sm.genWT[m * 32 + lane], sm.sP[wid][m], acc);
        sm.sKP[wid][lane] = acc;
      }
      __syncwarp();

      for (int t = lane; t < KP * H; t += 32) {
        const int k = t / H;
        const int h = t - k * H;
        const float dx = sm.sP[wid][h * 3 + 0] - sm.sKP[wid][k * 3 + 0];
        const float dy = sm.sP[wid][h * 3 + 1] - sm.sKP[wid][k * 3 + 1];
        const float dz = sm.sP[wid][h * 3 + 2] - sm.sKP[wid][k * 3 + 2];
        const float d  = sqrtf(fmaf(dx, dx, fmaf(dy, dy, dz * dz)));
        sm.swv[wid][h * 12 + k] = fmaxf(1.0f - d * INV_EXT, 0.0f);
      }
      __syncwarp();

      float2 acc[KP];
      #pragma unroll
      for (int k = 0; k < KP; ++k) acc[k] = make_float2(0.f, 0.f);

      #pragma unroll 2
      for (int h = 0; h < H; ++h) {
        const int jn = sm.sIdx[wid][h];
        const float2 xv =
            *reinterpret_cast<const float2*>(x + (size_t)jn * CIN + 2 * lane);
        const float4 w0 = *reinterpret_cast<const float4*>(&sm.swv[wid][h * 12]);
        const float4 w1 = *reinterpret_cast<const float4*>(&sm.swv[wid][h * 12 + 4]);
        const float2 w2 = *reinterpret_cast<const float2*>(&sm.swv[wid][h * 12 + 8]);
        const float wv[KP] = {w0.x, w0.y, w0.z, w0.w, w1.x, w1.y, w1.z, w1.w, w2.x, w2.y};
        #pragma unroll
        for (int k = 0; k < KP; ++k) {
          acc[k].x = fmaf(wv[k], xv.x, acc[k].x);
          acc[k].y = fmaf(wv[k], xv.y, acc[k].y);
        }
      }

      // Split weighted value into bf16 hi + bf16 residual lo.
      #pragma unroll
      for (int k = 0; k < KP; ++k) {
        const __nv_bfloat16 hx = __float2bfloat16(acc[k].x);
        const __nv_bfloat16 hy = __float2bfloat16(acc[k].y);
        const __nv_bfloat16 lx = __float2bfloat16(acc[k].x - __bfloat162float(hx));
        const __nv_bfloat16 ly = __float2bfloat16(acc[k].y - __bfloat162float(hy));
        const size_t off = (size_t)n * KDIM + k * CIN + 2 * lane;
        *reinterpret_cast<__nv_bfloat162*>(g_Ahi + off) = __halves2bfloat162(hx, hy);
        *reinterpret_cast<__nv_bfloat162*>(g_Alo + off) = __halves2bfloat162(lx, ly);
      }
    }
    __syncwarp();
  }
}

// ───────────────────── Kernel 2: B prep (transpose + split) ─────────────────────

__global__ void prep_b_kernel(const float* __restrict__ weights) {
  const int ki = blockIdx.x;       // 0..639
  const int o  = threadIdx.x;      // 0..127
  const float v = weights[(size_t)ki * COUT + o];
  const __nv_bfloat16 h = __float2bfloat16(v);
  const __nv_bfloat16 l = __float2bfloat16(v - __bfloat162float(h));
  g_Bhi[(size_t)o * KDIM + ki] = h;
  g_Blo[(size_t)o * KDIM + ki] = l;
}

// ───────────────────── Kernel 3: mma.sync GEMM out = A @ B^T ─────────────────────
// CTA: 128 rows x 128 cols. 8 warps in 2x4 grid, warp tile 64x32.
// K loop: 20 tiles of 32, cp.async double-buffered smem.
// Tiles in smem: 128 rows x 32 bf16 (64B data) with 80B pitch (conflict-free
// ldmatrix: 80B = 20 words, 8-row phases hit distinct banks).

constexpr int KT     = 32;                 // k per stage
constexpr int PITCH  = 80;                 // bytes per smem tile row
constexpr int TSZ    = 128 * PITCH;        // 10240 B per tile
constexpr int STAGE  = 4 * TSZ;            // Ahi,Alo,Bhi,Blo = 40960 B
constexpr int GSMEM  = 2 * STAGE;          // 81920 B
constexpr int NKT    = KDIM / KT;          // 20

__device__ __forceinline__ void cp16(uint32_t dst, const void* src) {
  asm volatile("cp.async.cg.shared.global [%0], [%1], 16;"
               :: "r"(dst), "l"(src) : "memory");
}
__device__ __forceinline__ void cp_commit() {
  asm volatile("cp.async.commit_group;" ::: "memory");
}
__device__ __forceinline__ void cp_wait1() {
  asm volatile("cp.async.wait_group 1;" ::: "memory");
}

__device__ __forceinline__ void ldm4(uint32_t* r, uint32_t addr) {
  asm volatile("ldmatrix.sync.aligned.m8n8.x4.shared.b16 {%0,%1,%2,%3}, [%4];"
               : "=r"(r[0]), "=r"(r[1]), "=r"(r[2]), "=r"(r[3]) : "r"(addr));
}

__device__ __forceinline__ void mma16816(float* d, const uint32_t* a,
                                         const uint32_t* b) {
  asm volatile(
      "mma.sync.aligned.m16n8k16.row.col.f32.bf16.bf16.f32 "
      "{%0,%1,%2,%3}, {%4,%5,%6,%7}, {%8,%9}, {%0,%1,%2,%3};"
      : "+f"(d[0]), "+f"(d[1]), "+f"(d[2]), "+f"(d[3])
      : "r"(a[0]), "r"(a[1]), "r"(a[2]), "r"(a[3]), "r"(b[0]), "r"(b[1]));
}

__global__ void __launch_bounds__(256, 1)
gemm_kernel(float* __restrict__ out, int N)
{
  extern __shared__ char sm[];
  const uint32_t sb = smem_u32(sm);
  const int tid  = threadIdx.x;
  const int lane = tid & 31;
  const int wid  = tid >> 5;
  const int wr   = wid >> 2;       // 0..1  -> rows wr*64
  const int wc   = wid & 3;        // 0..3  -> cols wc*32
  const size_t n0 = (size_t)blockIdx.x * 128;

  // cp.async mapping: tile = 128 rows x 4 chunks of 16B; 2 chunks per thread.
  const int id0 = tid, id1 = tid + 256;
  const int r0 = id0 >> 2, c0 = id0 & 3;
  const int r1 = id1 >> 2, c1 = id1 & 3;

  auto load_stage = [&](int st, int kc) {
    const uint32_t base = sb + st * STAGE;
    const size_t ga0 = (n0 + r0) * KDIM + kc * KT + c0 * 8;
    const size_t ga1 = (n0 + r1) * KDIM + kc * KT + c1 * 8;
    const size_t gb0 = (size_t)r0 * KDIM + kc * KT + c0 * 8;
    const size_t gb1 = (size_t)r1 * KDIM + kc * KT + c1 * 8;
    const uint32_t d0 = r0 * PITCH + c0 * 16;
    const uint32_t d1 = r1 * PITCH + c1 * 16;
    cp16(base + 0 * TSZ + d0, g_Ahi + ga0);
    cp16(base + 0 * TSZ + d1, g_Ahi + ga1);
    cp16(base + 1 * TSZ + d0, g_Alo + ga0);
    cp16(base + 1 * TSZ + d1, g_Alo + ga1);
    cp16(base + 2 * TSZ + d0, g_Bhi + gb0);
    cp16(base + 2 * TSZ + d1, g_Bhi + gb1);
    cp16(base + 3 * TSZ + d0, g_Blo + gb0);
    cp16(base + 3 * TSZ + d1, g_Blo + gb1);
  };

  load_stage(0, 0); cp_commit();
  load_stage(1, 1); cp_commit();

  // Per-lane ldmatrix address components.
  const int arow  = lane & 15;
  const int acolB = (lane >> 4) * 16;
  const int brow  = (lane & 7) + ((lane >> 4) << 3);
  const int bcolB = ((lane >> 3) & 1) * 16;

  float acc[4][4][4];
  #pragma unroll
  for (int mi = 0; mi < 4; ++mi)
    #pragma unroll
    for (int ni = 0; ni < 4; ++ni)
      #pragma unroll
      for (int j = 0; j < 4; ++j) acc[mi][ni][j] = 0.f;

  for (int kc = 0; kc < NKT; ++kc) {
    const int st = kc & 1;
    cp_wait1();
    __syncthreads();

    const uint32_t tAhi = sb + st * STAGE + 0 * TSZ;
    const uint32_t tAlo = sb + st * STAGE + 1 * TSZ;
    const uint32_t tBhi = sb + st * STAGE + 2 * TSZ;
    const uint32_t tBlo = sb + st * STAGE + 3 * TSZ;

    #pragma unroll
    for (int ks = 0; ks < 2; ++ks) {
      uint32_t ah[4][4], al[4][4], bh[4][2], bl[4][2];
      #pragma unroll
      for (int mi = 0; mi < 4; ++mi) {
        const uint32_t ao = (wr * 64 + mi * 16 + arow) * PITCH + ks * 32 + acolB;
        ldm4(ah[mi], tAhi + ao);
        ldm4(al[mi], tAlo + ao);
      }
      #pragma unroll
      for (int bi = 0; bi < 2; ++bi) {
        const uint32_t bo = (wc * 32 + bi * 16 + brow) * PITCH + ks * 32 + bcolB;
        uint32_t t4[4];
        ldm4(t4, tBhi + bo);
        bh[2 * bi][0] = t4[0]; bh[2 * bi][1] = t4[1];
        bh[2 * bi + 1][0] = t4[2]; bh[2 * bi + 1][1] = t4[3];
        ldm4(t4, tBlo + bo);
        bl[2 * bi][0] = t4[0]; bl[2 * bi][1] = t4[1];
        bl[2 * bi + 1][0] = t4[2]; bl[2 * bi + 1][1] = t4[3];
      }
      #pragma unroll
      for (int mi = 0; mi < 4; ++mi)
        #pragma unroll
        for (int ni = 0; ni < 4; ++ni) {
          mma16816(acc[mi][ni], ah[mi], bh[ni]);
          mma16816(acc[mi][ni], ah[mi], bl[ni]);
          mma16816(acc[mi][ni], al[mi], bh[ni]);
        }
    }

    __syncthreads();
    if (kc + 2 < NKT) load_stage(st, kc + 2);
    cp_commit();
  }

  // Epilogue: direct global stores (float2 per fragment half).
  const int trow = lane >> 2;
  const int tcol = (lane & 3) * 2;
  #pragma unroll
  for (int mi = 0; mi < 4; ++mi) {
    const size_t row = n0 + wr * 64 + mi * 16 + trow;
    #pragma unroll
    for (int ni = 0; ni < 4; ++ni) {
      const int col = wc * 32 + ni * 8 + tcol;
      if (row < (size_t)N) {
        *reinterpret_cast<float2*>(out + row * COUT + col) =
            make_float2(acc[mi][ni][0], acc[mi][ni][1]);
        *reinterpret_cast<float2*>(out + (row + 8) * COUT + col) =
            make_float2(acc[mi][ni][2], acc[mi][ni][3]);
      }
    }
  }
}

}  // namespace

// ───────────────────────────── launch ─────────────────────────────

extern "C" void kernel_launch(void* const* d_in, const int* in_sizes, int n_in,
                              void* d_out, int out_size) {
  const float* q_pts = (const float*)d_in[0];
  const float* s_pts = (const float*)d_in[1];
  const float* x     = (const float*)d_in[2];
  const float* genW  = (const float*)d_in[3];
  const float* genB  = (const float*)d_in[4];
  const float* wts   = (const float*)d_in[5];
  const int*   inds  = (const int*)d_in[6];
  float* out = (float*)d_out;

  int N  = in_sizes[0] / 3;
  const int Ns = in_sizes[1] / 3;
  if (N > MAXN) N = MAXN;

  cudaFuncSetAttribute(gemm_kernel,
                       cudaFuncAttributeMaxDynamicSharedMemorySize, GSMEM);

  prep_b_kernel<<<KDIM, COUT>>>(wts);

  const int grid1 = (N + TILE - 1) / TILE;
  producer_kernel<<<grid1, NT>>>(q_pts, s_pts, x, genW, genB, inds, N, Ns);

  const int grid3 = (N + 127) / 128;
  gemm_kernel<<<grid3, 256, GSMEM>>>(out, N);
}

// round 4
// speedup vs baseline: 1.8471x; 1.0464x over previous
#include <cuda_runtime.h>
#include <cuda_bf16.h>
#include <cstdint>

// ─────────────────────────────────────────────────────────────────────────────
// KPConv: producer (gather + kernel-point weights + phase-4 reduction, using
// packed fp32 FFMA2) writes weighted features as bf16 hi/lo split pair;
// mma.sync (HMMA) GEMM with 3-way split product computes out = weighted @ W.
// tcgen05 unavailable (harness PTX target is sm_103, not sm_103a).
// ─────────────────────────────────────────────────────────────────────────────

namespace {

typedef unsigned long long u64;

constexpr int H    = 26;
constexpr int PADH = 28;
constexpr int KP   = 10;
constexpr int CIN  = 64;
constexpr int COUT = 128;
constexpr int KDIM = KP * CIN;   // 640
constexpr int TILE = 32;
constexpr int NT   = 256;
constexpr float INV_EXT = 1.0f / 1.2f;
constexpr int MAXN = 65536;

// Scratch (device-global: no allocation allowed in kernel_launch).
__device__ __nv_bfloat16 g_Ahi[(size_t)MAXN * KDIM];
__device__ __nv_bfloat16 g_Alo[(size_t)MAXN * KDIM];
__device__ __nv_bfloat16 g_Bhi[(size_t)COUT * KDIM];   // [o][k*64+i]
__device__ __nv_bfloat16 g_Blo[(size_t)COUT * KDIM];

__device__ __forceinline__ uint32_t smem_u32(const void* p) {
  uint32_t a;
  asm("{ .reg .u64 t; cvta.to.shared.u64 t, %1; cvt.u32.u64 %0, t; }"
      : "=r"(a) : "l"(p));
  return a;
}

// Packed 2xfp32 ops (sm_100+ base PTX).
__device__ __forceinline__ u64 ffma2(u64 a, u64 b, u64 c) {
  u64 d;
  asm("fma.rn.f32x2 %0, %1, %2, %3;" : "=l"(d) : "l"(a), "l"(b), "l"(c));
  return d;
}
__device__ __forceinline__ u64 pack2(float lo, float hi) {
  u64 d;
  asm("mov.b64 %0, {%1, %2};" : "=l"(d) : "f"(lo), "f"(hi));
  return d;
}
__device__ __forceinline__ float2 unpack2(u64 v) {
  float2 r;
  asm("mov.b64 {%0, %1}, %2;" : "=f"(r.x), "=f"(r.y) : "l"(v));
  return r;
}

// ───────────────────── Kernel 1: producer (+ folded B prep) ─────────────────────

struct P1Smem {
  u64   genWT2[42 * 32];       // [m2][j]: packed (W[2m2][j], W[2m2+1][j])
  float genB[32];
  float sP[8][84];             // 336 B per row, 8B-aligned pairs at even idx
  float sKP[8][32];
  alignas(16) float swv[8][H * 12];  // [h][k], 48 B per h -> 8B-aligned k-pairs
  int   sIdx[8][H];
};

constexpr int PREPB = 64;      // blocks that also transpose/split W

__global__ void __launch_bounds__(NT, 3)
producer_kernel(const float* __restrict__ q_pts,
                const float* __restrict__ s_pts,
                const float* __restrict__ x,
                const float* __restrict__ genW,
                const float* __restrict__ genB,
                const float* __restrict__ weights,
                const int*   __restrict__ inds,
                int N, int Ns)
{
  __shared__ P1Smem sm;
  const int tid  = threadIdx.x;
  const int lane = tid & 31;
  const int wid  = tid >> 5;

  // Folded B prep: first PREPB blocks split/transpose W (write-coalesced).
  if (blockIdx.x < PREPB) {
    for (int t = blockIdx.x * NT + tid; t < KDIM * COUT; t += PREPB * NT) {
      const int o  = t / KDIM;
      const int ki = t - o * KDIM;
      const float v = weights[(size_t)ki * COUT + o];
      const __nv_bfloat16 hh = __float2bfloat16(v);
      const __nv_bfloat16 ll = __float2bfloat16(v - __bfloat162float(hh));
      g_Bhi[t] = hh;
      g_Blo[t] = ll;
    }
  }

  // Stage gen_W as packed m-pairs: genWT2[m2*32+j] = (W[j][2m2], W[j][2m2+1]).
  for (int t = tid; t < 42 * 32; t += NT) {
    const int j  = t & 31;
    const int m2 = t >> 5;
    if (j < 30)
      sm.genWT2[t] = pack2(genW[j * 84 + 2 * m2], genW[j * 84 + 2 * m2 + 1]);
    else
      sm.genWT2[t] = 0;
  }
  if (tid < 30) sm.genB[tid] = genB[tid];
  __syncthreads();

  const int n_base = blockIdx.x * TILE;

  for (int it = 0; it < TILE / 8; ++it) {
    const int p = wid * (TILE / 8) + it;
    const int n = n_base + p;
    if (n < N) {
      const float qx = q_pts[3 * n + 0];
      const float qy = q_pts[3 * n + 1];
      const float qz = q_pts[3 * n + 2];

      // Phase 1: neighbor gather into padded 84-vector.
      if (lane < H) {
        int j = inds[(size_t)n * H + lane];
        float sx, sy, sz;
        if (j >= 0 && j < Ns) {
          sx = s_pts[3 * j + 0];
          sy = s_pts[3 * j + 1];
          sz = s_pts[3 * j + 2];
        } else {
          sx = sy = sz = 1e6f;   // shadow point -> zero influence
          j = 0;
        }
        sm.sP[wid][lane * 3 + 0] = sx - qx;
        sm.sP[wid][lane * 3 + 1] = sy - qy;
        sm.sP[wid][lane * 3 + 2] = sz - qz;
        sm.sIdx[wid][lane] = j;
      } else if (lane < PADH) {
        const int b = lane - H;
        sm.sP[wid][78 + b * 3 + 0] = -1.0f;
        sm.sP[wid][78 + b * 3 + 1] = -1.0f;
        sm.sP[wid][78 + b * 3 + 2] = -1.0f;
      }
      __syncwarp();

      // Phase 2: kp = gen_W @ p + gen_b, packed 2-wide over m.
      if (lane < 30) {
        u64 acc2 = 0;   // (0.f, 0.f)
        const u64* pp = reinterpret_cast<const u64*>(&sm.sP[wid][0]);
        #pragma unroll 6
        for (int m2 = 0; m2 < 42; ++m2)
          acc2 = ffma2(sm.genWT2[m2 * 32 + lane], pp[m2], acc2);
        const float2 r = unpack2(acc2);
        sm.sKP[wid][lane] = r.x + r.y + sm.genB[lane];
      }
      __syncwarp();

      // Phase 3: influence weights w[h][k] = relu(1 - ||nbr - kp|| / ext).
      for (int t = lane; t < KP * H; t += 32) {
        const int k = t / H;
        const int h = t - k * H;
        const float dx = sm.sP[wid][h * 3 + 0] - sm.sKP[wid][k * 3 + 0];
        const float dy = sm.sP[wid][h * 3 + 1] - sm.sKP[wid][k * 3 + 1];
        const float dz = sm.sP[wid][h * 3 + 2] - sm.sKP[wid][k * 3 + 2];
        const float d  = sqrtf(fmaf(dx, dx, fmaf(dy, dy, dz * dz)));
        sm.swv[wid][h * 12 + k] = fmaxf(1.0f - d * INV_EXT, 0.0f);
      }
      __syncwarp();

      // Phase 4: weighted[k][c] = sum_h w[k][h] * x[idx[h]][c],
      // packed over k-pairs: acc2[kk][c] = (k=2kk, k=2kk+1) for column c.
      u64 acc2[5][2];
      #pragma unroll
      for (int kk = 0; kk < 5; ++kk) { acc2[kk][0] = 0; acc2[kk][1] = 0; }

      #pragma unroll 2
      for (int h = 0; h < H; ++h) {
        const int jn = sm.sIdx[wid][h];
        const float2 xv =
            *reinterpret_cast<const float2*>(x + (size_t)jn * CIN + 2 * lane);
        const u64 x0 = pack2(xv.x, xv.x);
        const u64 x1 = pack2(xv.y, xv.y);
        const u64* wp = reinterpret_cast<const u64*>(&sm.swv[wid][h * 12]);
        #pragma unroll
        for (int kk = 0; kk < 5; ++kk) {
          const u64 w2 = wp[kk];          // (w[2kk], w[2kk+1]) broadcast
          acc2[kk][0] = ffma2(w2, x0, acc2[kk][0]);
          acc2[kk][1] = ffma2(w2, x1, acc2[kk][1]);
        }
      }

      // Split into bf16 hi + residual lo and store.
      #pragma unroll
      for (int kk = 0; kk < 5; ++kk) {
        const float2 a0 = unpack2(acc2[kk][0]);   // col c0: (k even, k odd)
        const float2 a1 = unpack2(acc2[kk][1]);   // col c1
        const float ve[2] = {a0.x, a1.x};          // k = 2kk   : (c0, c1)
        const float vo[2] = {a0.y, a1.y};          // k = 2kk+1 : (c0, c1)
        #pragma unroll
        for (int e = 0; e < 2; ++e) {
          const float* v = e ? vo : ve;
          const int k = 2 * kk + e;
          const __nv_bfloat162 hi2 =
              __floats2bfloat162_rn(v[0], v[1]);
          const float2 hif = __bfloat1622float2(hi2);
          const __nv_bfloat162 lo2 =
              __floats2bfloat162_rn(v[0] - hif.x, v[1] - hif.y);
          const size_t off = (size_t)n * KDIM + k * CIN + 2 * lane;
          *reinterpret_cast<__nv_bfloat162*>(g_Ahi + off) = hi2;
          *reinterpret_cast<__nv_bfloat162*>(g_Alo + off) = lo2;
        }
      }
    }
    __syncwarp();
  }
}

// ───────────────────── Kernel 2: mma.sync GEMM out = A @ B^T ─────────────────────
// CTA: 128 rows x 128 cols. 8 warps 2x4, warp tile 64x32.
// 20 K-tiles of 32, cp.async double-buffered. 80B smem pitch (conflict-free).

constexpr int KT     = 32;
constexpr int PITCH  = 80;
constexpr int TSZ    = 128 * PITCH;
constexpr int STAGE  = 4 * TSZ;
constexpr int GSMEM  = 2 * STAGE;          // 81920 B
constexpr int NKT    = KDIM / KT;          // 20

__device__ __forceinline__ void cp16(uint32_t dst, const void* src) {
  asm volatile("cp.async.cg.shared.global [%0], [%1], 16;"
               :: "r"(dst), "l"(src) : "memory");
}
__device__ __forceinline__ void cp_commit() {
  asm volatile("cp.async.commit_group;" ::: "memory");
}
__device__ __forceinline__ void cp_wait1() {
  asm volatile("cp.async.wait_group 1;" ::: "memory");
}

__device__ __forceinline__ void ldm4(uint32_t* r, uint32_t addr) {
  asm volatile("ldmatrix.sync.aligned.m8n8.x4.shared.b16 {%0,%1,%2,%3}, [%4];"
               : "=r"(r[0]), "=r"(r[1]), "=r"(r[2]), "=r"(r[3]) : "r"(addr));
}

__device__ __forceinline__ void mma16816(float* d, const uint32_t* a,
                                         const uint32_t* b) {
  asm volatile(
      "mma.sync.aligned.m16n8k16.row.col.f32.bf16.bf16.f32 "
      "{%0,%1,%2,%3}, {%4,%5,%6,%7}, {%8,%9}, {%0,%1,%2,%3};"
      : "+f"(d[0]), "+f"(d[1]), "+f"(d[2]), "+f"(d[3])
      : "r"(a[0]), "r"(a[1]), "r"(a[2]), "r"(a[3]), "r"(b[0]), "r"(b[1]));
}

__global__ void __launch_bounds__(256, 1)
gemm_kernel(float* __restrict__ out, int N)
{
  extern __shared__ char sm[];
  const uint32_t sb = smem_u32(sm);
  const int tid  = threadIdx.x;
  const int lane = tid & 31;
  const int wid  = tid >> 5;
  const int wr   = wid >> 2;
  const int wc   = wid & 3;
  const size_t n0 = (size_t)blockIdx.x * 128;

  const int id0 = tid, id1 = tid + 256;
  const int r0 = id0 >> 2, c0 = id0 & 3;
  const int r1 = id1 >> 2, c1 = id1 & 3;

  auto load_stage = [&](int st, int kc) {
    const uint32_t base = sb + st * STAGE;
    const size_t ga0 = (n0 + r0) * KDIM + kc * KT + c0 * 8;
    const size_t ga1 = (n0 + r1) * KDIM + kc * KT + c1 * 8;
    const size_t gb0 = (size_t)r0 * KDIM + kc * KT + c0 * 8;
    const size_t gb1 = (size_t)r1 * KDIM + kc * KT + c1 * 8;
    const uint32_t d0 = r0 * PITCH + c0 * 16;
    const uint32_t d1 = r1 * PITCH + c1 * 16;
    cp16(base + 0 * TSZ + d0, g_Ahi + ga0);
    cp16(base + 0 * TSZ + d1, g_Ahi + ga1);
    cp16(base + 1 * TSZ + d0, g_Alo + ga0);
    cp16(base + 1 * TSZ + d1, g_Alo + ga1);
    cp16(base + 2 * TSZ + d0, g_Bhi + gb0);
    cp16(base + 2 * TSZ + d1, g_Bhi + gb1);
    cp16(base + 3 * TSZ + d0, g_Blo + gb0);
    cp16(base + 3 * TSZ + d1, g_Blo + gb1);
  };

  load_stage(0, 0); cp_commit();
  load_stage(1, 1); cp_commit();

  const int arow  = lane & 15;
  const int acolB = (lane >> 4) * 16;
  const int brow  = (lane & 7) + ((lane >> 4) << 3);
  const int bcolB = ((lane >> 3) & 1) * 16;

  float acc[4][4][4];
  #pragma unroll
  for (int mi = 0; mi < 4; ++mi)
    #pragma unroll
    for (int ni = 0; ni < 4; ++ni)
      #pragma unroll
      for (int j = 0; j < 4; ++j) acc[mi][ni][j] = 0.f;

  for (int kc = 0; kc < NKT; ++kc) {
    const int st = kc & 1;
    cp_wait1();
    __syncthreads();

    const uint32_t tAhi = sb + st * STAGE + 0 * TSZ;
    const uint32_t tAlo = sb + st * STAGE + 1 * TSZ;
    const uint32_t tBhi = sb + st * STAGE + 2 * TSZ;
    const uint32_t tBlo = sb + st * STAGE + 3 * TSZ;

    #pragma unroll
    for (int ks = 0; ks < 2; ++ks) {
      uint32_t ah[4][4], al[4][4], bh[4][2], bl[4][2];
      #pragma unroll
      for (int mi = 0; mi < 4; ++mi) {
        const uint32_t ao = (wr * 64 + mi * 16 + arow) * PITCH + ks * 32 + acolB;
        ldm4(ah[mi], tAhi + ao);
        ldm4(al[mi], tAlo + ao);
      }
      #pragma unroll
      for (int bi = 0; bi < 2; ++bi) {
        const uint32_t bo = (wc * 32 + bi * 16 + brow) * PITCH + ks * 32 + bcolB;
        uint32_t t4[4];
        ldm4(t4, tBhi + bo);
        bh[2 * bi][0] = t4[0]; bh[2 * bi][1] = t4[1];
        bh[2 * bi + 1][0] = t4[2]; bh[2 * bi + 1][1] = t4[3];
        ldm4(t4, tBlo + bo);
        bl[2 * bi][0] = t4[0]; bl[2 * bi][1] = t4[1];
        bl[2 * bi + 1][0] = t4[2]; bl[2 * bi + 1][1] = t4[3];
      }
      #pragma unroll
      for (int mi = 0; mi < 4; ++mi)
        #pragma unroll
        for (int ni = 0; ni < 4; ++ni) {
          mma16816(acc[mi][ni], ah[mi], bh[ni]);
          mma16816(acc[mi][ni], ah[mi], bl[ni]);
          mma16816(acc[mi][ni], al[mi], bh[ni]);
        }
    }

    __syncthreads();
    if (kc + 2 < NKT) load_stage(st, kc + 2);
    cp_commit();
  }

  const int trow = lane >> 2;
  const int tcol = (lane & 3) * 2;
  #pragma unroll
  for (int mi = 0; mi < 4; ++mi) {
    const size_t row = n0 + wr * 64 + mi * 16 + trow;
    #pragma unroll
    for (int ni = 0; ni < 4; ++ni) {
      const int col = wc * 32 + ni * 8 + tcol;
      if (row < (size_t)N) {
        *reinterpret_cast<float2*>(out + row * COUT + col) =
            make_float2(acc[mi][ni][0], acc[mi][ni][1]);
        *reinterpret_cast<float2*>(out + (row + 8) * COUT + col) =
            make_float2(acc[mi][ni][2], acc[mi][ni][3]);
      }
    }
  }
}

}  // namespace

// ───────────────────────────── launch ─────────────────────────────

extern "C" void kernel_launch(void* const* d_in, const int* in_sizes, int n_in,
                              void* d_out, int out_size) {
  const float* q_pts = (const float*)d_in[0];
  const float* s_pts = (const float*)d_in[1];
  const float* x     = (const float*)d_in[2];
  const float* genW  = (const float*)d_in[3];
  const float* genB  = (const float*)d_in[4];
  const float* wts   = (const float*)d_in[5];
  const int*   inds  = (const int*)d_in[6];
  float* out = (float*)d_out;

  int N  = in_sizes[0] / 3;
  const int Ns = in_sizes[1] / 3;
  if (N > MAXN) N = MAXN;

  cudaFuncSetAttribute(gemm_kernel,
                       cudaFuncAttributeMaxDynamicSharedMemorySize, GSMEM);

  const int grid1 = (N + TILE - 1) / TILE;
  producer_kernel<<<grid1, NT>>>(q_pts, s_pts, x, genW, genB, wts, inds, N, Ns);

  const int grid3 = (N + 127) / 128;
  gemm_kernel<<<grid3, 256, GSMEM>>>(out, N);
}

// round 5
// speedup vs baseline: 1.9558x; 1.0589x over previous
#include <cuda_runtime.h>
#include <cuda_bf16.h>
#include <cstdint>

// ─────────────────────────────────────────────────────────────────────────────
// KPConv: producer (gather + kernel-point weights + MLP-batched phase-4
// reduction with packed fp32 FFMA2) writes weighted features as bf16 hi/lo
// split pair; mma.sync (HMMA) GEMM with 3-way split product and a 4-stage
// cp.async pipeline computes out = weighted @ W.
// tcgen05 unavailable (harness PTX target is sm_103, not sm_103a).
// ─────────────────────────────────────────────────────────────────────────────

namespace {

typedef unsigned long long u64;

constexpr int H    = 26;
constexpr int PADH = 28;
constexpr int KP   = 10;
constexpr int CIN  = 64;
constexpr int COUT = 128;
constexpr int KDIM = KP * CIN;   // 640
constexpr int TILE = 32;
constexpr int NT   = 256;
constexpr float INV_EXT = 1.0f / 1.2f;
constexpr int MAXN = 65536;

// Scratch (device-global: no allocation allowed in kernel_launch).
__device__ __nv_bfloat16 g_Ahi[(size_t)MAXN * KDIM];
__device__ __nv_bfloat16 g_Alo[(size_t)MAXN * KDIM];
__device__ __nv_bfloat16 g_Bhi[(size_t)COUT * KDIM];   // [o][k*64+i]
__device__ __nv_bfloat16 g_Blo[(size_t)COUT * KDIM];

__device__ __forceinline__ uint32_t smem_u32(const void* p) {
  uint32_t a;
  asm("{ .reg .u64 t; cvta.to.shared.u64 t, %1; cvt.u32.u64 %0, t; }"
      : "=r"(a) : "l"(p));
  return a;
}

// Packed 2xfp32 ops (sm_100+ base PTX).
__device__ __forceinline__ u64 ffma2(u64 a, u64 b, u64 c) {
  u64 d;
  asm("fma.rn.f32x2 %0, %1, %2, %3;" : "=l"(d) : "l"(a), "l"(b), "l"(c));
  return d;
}
__device__ __forceinline__ u64 pack2(float lo, float hi) {
  u64 d;
  asm("mov.b64 %0, {%1, %2};" : "=l"(d) : "f"(lo), "f"(hi));
  return d;
}
__device__ __forceinline__ float2 unpack2(u64 v) {
  float2 r;
  asm("mov.b64 {%0, %1}, %2;" : "=f"(r.x), "=f"(r.y) : "l"(v));
  return r;
}

// ───────────────────── Kernel 1: producer (+ folded B prep) ─────────────────────

struct P1Smem {
  u64   genWT2[42 * 32];       // [m2][j]: packed (W[2m2][j], W[2m2+1][j])
  float genB[32];
  float sP[8][84];
  float sKP[8][32];
  alignas(16) float swv[8][H * 12];  // [h][k]
  int   sIdx[8][H];
};

constexpr int PREPB = 64;      // blocks that also transpose/split W

__global__ void __launch_bounds__(NT, 2)
producer_kernel(const float* __restrict__ q_pts,
                const float* __restrict__ s_pts,
                const float* __restrict__ x,
                const float* __restrict__ genW,
                const float* __restrict__ genB,
                const float* __restrict__ weights,
                const int*   __restrict__ inds,
                int N, int Ns)
{
  __shared__ P1Smem sm;
  const int tid  = threadIdx.x;
  const int lane = tid & 31;
  const int wid  = tid >> 5;

  // Folded B prep: first PREPB blocks split/transpose W (write-coalesced).
  if (blockIdx.x < PREPB) {
    for (int t = blockIdx.x * NT + tid; t < KDIM * COUT; t += PREPB * NT) {
      const int o  = t / KDIM;
      const int ki = t - o * KDIM;
      const float v = weights[(size_t)ki * COUT + o];
      const __nv_bfloat16 hh = __float2bfloat16(v);
      const __nv_bfloat16 ll = __float2bfloat16(v - __bfloat162float(hh));
      g_Bhi[t] = hh;
      g_Blo[t] = ll;
    }
  }

  // Stage gen_W as packed m-pairs.
  for (int t = tid; t < 42 * 32; t += NT) {
    const int j  = t & 31;
    const int m2 = t >> 5;
    if (j < 30)
      sm.genWT2[t] = pack2(genW[j * 84 + 2 * m2], genW[j * 84 + 2 * m2 + 1]);
    else
      sm.genWT2[t] = 0;
  }
  if (tid < 30) sm.genB[tid] = genB[tid];
  __syncthreads();

  const int n_base = blockIdx.x * TILE;

  for (int it = 0; it < TILE / 8; ++it) {
    const int p = wid * (TILE / 8) + it;
    const int n = n_base + p;
    if (n < N) {
      const float qx = q_pts[3 * n + 0];
      const float qy = q_pts[3 * n + 1];
      const float qz = q_pts[3 * n + 2];

      // Phase 1: neighbor gather into padded 84-vector.
      if (lane < H) {
        int j = inds[(size_t)n * H + lane];
        float sx, sy, sz;
        if (j >= 0 && j < Ns) {
          sx = s_pts[3 * j + 0];
          sy = s_pts[3 * j + 1];
          sz = s_pts[3 * j + 2];
        } else {
          sx = sy = sz = 1e6f;   // shadow point -> zero influence
          j = 0;
        }
        sm.sP[wid][lane * 3 + 0] = sx - qx;
        sm.sP[wid][lane * 3 + 1] = sy - qy;
        sm.sP[wid][lane * 3 + 2] = sz - qz;
        sm.sIdx[wid][lane] = j;
      } else if (lane < PADH) {
        const int b = lane - H;
        sm.sP[wid][78 + b * 3 + 0] = -1.0f;
        sm.sP[wid][78 + b * 3 + 1] = -1.0f;
        sm.sP[wid][78 + b * 3 + 2] = -1.0f;
      }
      __syncwarp();

      // Phase 2: kp = gen_W @ p + gen_b, packed 2-wide over m.
      if (lane < 30) {
        u64 acc2 = 0;
        const u64* pp = reinterpret_cast<const u64*>(&sm.sP[wid][0]);
        #pragma unroll 6
        for (int m2 = 0; m2 < 42; ++m2)
          acc2 = ffma2(sm.genWT2[m2 * 32 + lane], pp[m2], acc2);
        const float2 r = unpack2(acc2);
        sm.sKP[wid][lane] = r.x + r.y + sm.genB[lane];
      }
      __syncwarp();

      // Phase 3: influence weights w[h][k] = relu(1 - ||nbr - kp|| / ext).
      for (int t = lane; t < KP * H; t += 32) {
        const int k = t / H;
        const int h = t - k * H;
        const float dx = sm.sP[wid][h * 3 + 0] - sm.sKP[wid][k * 3 + 0];
        const float dy = sm.sP[wid][h * 3 + 1] - sm.sKP[wid][k * 3 + 1];
        const float dz = sm.sP[wid][h * 3 + 2] - sm.sKP[wid][k * 3 + 2];
        const float d  = sqrtf(fmaf(dx, dx, fmaf(dy, dy, dz * dz)));
        sm.swv[wid][h * 12 + k] = fmaxf(1.0f - d * INV_EXT, 0.0f);
      }
      __syncwarp();

      // Phase 4: weighted[k][c] = sum_h w[k][h] * x[idx[h]][c].
      // MLP batching: 2 halves of 13 independent gathers each, loads issued
      // before any consumer FFMA2 (latency /13 instead of /2).
      u64 acc2[5][2];
      #pragma unroll
      for (int kk = 0; kk < 5; ++kk) { acc2[kk][0] = 0; acc2[kk][1] = 0; }

      #pragma unroll
      for (int half = 0; half < 2; ++half) {
        const int hb = half * 13;
        float2 xb[13];
        #pragma unroll
        for (int hh = 0; hh < 13; ++hh) {
          const int jn = sm.sIdx[wid][hb + hh];
          xb[hh] = *reinterpret_cast<const float2*>(
              x + (size_t)jn * CIN + 2 * lane);
        }
        #pragma unroll
        for (int hh = 0; hh < 13; ++hh) {
          const u64 x0 = pack2(xb[hh].x, xb[hh].x);
          const u64 x1 = pack2(xb[hh].y, xb[hh].y);
          const u64* wp =
              reinterpret_cast<const u64*>(&sm.swv[wid][(hb + hh) * 12]);
          #pragma unroll
          for (int kk = 0; kk < 5; ++kk) {
            const u64 w2 = wp[kk];
            acc2[kk][0] = ffma2(w2, x0, acc2[kk][0]);
            acc2[kk][1] = ffma2(w2, x1, acc2[kk][1]);
          }
        }
      }

      // Split into bf16 hi + residual lo and store.
      #pragma unroll
      for (int kk = 0; kk < 5; ++kk) {
        const float2 a0 = unpack2(acc2[kk][0]);
        const float2 a1 = unpack2(acc2[kk][1]);
        const float ve[2] = {a0.x, a1.x};
        const float vo[2] = {a0.y, a1.y};
        #pragma unroll
        for (int e = 0; e < 2; ++e) {
          const float* v = e ? vo : ve;
          const int k = 2 * kk + e;
          const __nv_bfloat162 hi2 = __floats2bfloat162_rn(v[0], v[1]);
          const float2 hif = __bfloat1622float2(hi2);
          const __nv_bfloat162 lo2 =
              __floats2bfloat162_rn(v[0] - hif.x, v[1] - hif.y);
          const size_t off = (size_t)n * KDIM + k * CIN + 2 * lane;
          *reinterpret_cast<__nv_bfloat162*>(g_Ahi + off) = hi2;
          *reinterpret_cast<__nv_bfloat162*>(g_Alo + off) = lo2;
        }
      }
    }
    __syncwarp();
  }
}

// ───────────────────── Kernel 2: mma.sync GEMM out = A @ B^T ─────────────────────
// CTA: 128 rows x 128 cols. 8 warps 2x4, warp tile 64x32.
// 20 K-tiles of 32, 4-stage cp.async ring, ONE __syncthreads per tile.
// 80B smem pitch (conflict-free ldmatrix).

constexpr int KT      = 32;
constexpr int PITCH   = 80;
constexpr int TSZ     = 128 * PITCH;
constexpr int STAGE   = 4 * TSZ;          // Ahi,Alo,Bhi,Blo = 40960 B
constexpr int NSTAGES = 4;
constexpr int GSMEM   = NSTAGES * STAGE;  // 163840 B
constexpr int NKT     = KDIM / KT;        // 20

__device__ __forceinline__ void cp16(uint32_t dst, const void* src) {
  asm volatile("cp.async.cg.shared.global [%0], [%1], 16;"
               :: "r"(dst), "l"(src) : "memory");
}
__device__ __forceinline__ void cp_commit() {
  asm volatile("cp.async.commit_group;" ::: "memory");
}
__device__ __forceinline__ void cp_wait2() {
  asm volatile("cp.async.wait_group 2;" ::: "memory");
}

__device__ __forceinline__ void ldm4(uint32_t* r, uint32_t addr) {
  asm volatile("ldmatrix.sync.aligned.m8n8.x4.shared.b16 {%0,%1,%2,%3}, [%4];"
               : "=r"(r[0]), "=r"(r[1]), "=r"(r[2]), "=r"(r[3]) : "r"(addr));
}

__device__ __forceinline__ void mma16816(float* d, const uint32_t* a,
                                         const uint32_t* b) {
  asm volatile(
      "mma.sync.aligned.m16n8k16.row.col.f32.bf16.bf16.f32 "
      "{%0,%1,%2,%3}, {%4,%5,%6,%7}, {%8,%9}, {%0,%1,%2,%3};"
      : "+f"(d[0]), "+f"(d[1]), "+f"(d[2]), "+f"(d[3])
      : "r"(a[0]), "r"(a[1]), "r"(a[2]), "r"(a[3]), "r"(b[0]), "r"(b[1]));
}

__global__ void __launch_bounds__(256, 1)
gemm_kernel(float* __restrict__ out, int N)
{
  extern __shared__ char sm[];
  const uint32_t sb = smem_u32(sm);
  const int tid  = threadIdx.x;
  const int lane = tid & 31;
  const int wid  = tid >> 5;
  const int wr   = wid >> 2;
  const int wc   = wid & 3;
  const size_t n0 = (size_t)blockIdx.x * 128;

  const int id0 = tid, id1 = tid + 256;
  const int r0 = id0 >> 2, c0 = id0 & 3;
  const int r1 = id1 >> 2, c1 = id1 & 3;

  auto load_stage = [&](int st, int kc) {
    const uint32_t base = sb + st * STAGE;
    const size_t ga0 = (n0 + r0) * KDIM + kc * KT + c0 * 8;
    const size_t ga1 = (n0 + r1) * KDIM + kc * KT + c1 * 8;
    const size_t gb0 = (size_t)r0 * KDIM + kc * KT + c0 * 8;
    const size_t gb1 = (size_t)r1 * KDIM + kc * KT + c1 * 8;
    const uint32_t d0 = r0 * PITCH + c0 * 16;
    const uint32_t d1 = r1 * PITCH + c1 * 16;
    cp16(base + 0 * TSZ + d0, g_Ahi + ga0);
    cp16(base + 0 * TSZ + d1, g_Ahi + ga1);
    cp16(base + 1 * TSZ + d0, g_Alo + ga0);
    cp16(base + 1 * TSZ + d1, g_Alo + ga1);
    cp16(base + 2 * TSZ + d0, g_Bhi + gb0);
    cp16(base + 2 * TSZ + d1, g_Bhi + gb1);
    cp16(base + 3 * TSZ + d0, g_Blo + gb0);
    cp16(base + 3 * TSZ + d1, g_Blo + gb1);
  };

  load_stage(0, 0); cp_commit();
  load_stage(1, 1); cp_commit();
  load_stage(2, 2); cp_commit();

  const int arow  = lane & 15;
  const int acolB = (lane >> 4) * 16;
  const int brow  = (lane & 7) + ((lane >> 4) << 3);
  const int bcolB = ((lane >> 3) & 1) * 16;

  float acc[4][4][4];
  #pragma unroll
  for (int mi = 0; mi < 4; ++mi)
    #pragma unroll
    for (int ni = 0; ni < 4; ++ni)
      #pragma unroll
      for (int j = 0; j < 4; ++j) acc[mi][ni][j] = 0.f;

  for (int kc = 0; kc < NKT; ++kc) {
    const int st = kc & (NSTAGES - 1);
    cp_wait2();          // stage kc resident (only kc+1, kc+2 may be pending)
    __syncthreads();     // all warps done with slot being overwritten below

    // Prefetch stage kc+3 into slot (kc-1)%4 — safe: everyone passed sync.
    if (kc + 3 < NKT) load_stage((kc + 3) & (NSTAGES - 1), kc + 3);
    cp_commit();

    const uint32_t tAhi = sb + st * STAGE + 0 * TSZ;
    const uint32_t tAlo = sb + st * STAGE + 1 * TSZ;
    const uint32_t tBhi = sb + st * STAGE + 2 * TSZ;
    const uint32_t tBlo = sb + st * STAGE + 3 * TSZ;

    #pragma unroll
    for (int ks = 0; ks < 2; ++ks) {
      uint32_t ah[4][4], al[4][4], bh[4][2], bl[4][2];
      #pragma unroll
      for (int mi = 0; mi < 4; ++mi) {
        const uint32_t ao = (wr * 64 + mi * 16 + arow) * PITCH + ks * 32 + acolB;
        ldm4(ah[mi], tAhi + ao);
        ldm4(al[mi], tAlo + ao);
      }
      #pragma unroll
      for (int bi = 0; bi < 2; ++bi) {
        const uint32_t bo = (wc * 32 + bi * 16 + brow) * PITCH + ks * 32 + bcolB;
        uint32_t t4[4];
        ldm4(t4, tBhi + bo);
        bh[2 * bi][0] = t4[0]; bh[2 * bi][1] = t4[1];
        bh[2 * bi + 1][0] = t4[2]; bh[2 * bi + 1][1] = t4[3];
        ldm4(t4, tBlo + bo);
        bl[2 * bi][0] = t4[0]; bl[2 * bi][1] = t4[1];
        bl[2 * bi + 1][0] = t4[2]; bl[2 * bi + 1][1] = t4[3];
      }
      #pragma unroll
      for (int mi = 0; mi < 4; ++mi)
        #pragma unroll
        for (int ni = 0; ni < 4; ++ni) {
          mma16816(acc[mi][ni], ah[mi], bh[ni]);
          mma16816(acc[mi][ni], ah[mi], bl[ni]);
          mma16816(acc[mi][ni], al[mi], bh[ni]);
        }
    }
  }

  const int trow = lane >> 2;
  const int tcol = (lane & 3) * 2;
  #pragma unroll
  for (int mi = 0; mi < 4; ++mi) {
    const size_t row = n0 + wr * 64 + mi * 16 + trow;
    #pragma unroll
    for (int ni = 0; ni < 4; ++ni) {
      const int col = wc * 32 + ni * 8 + tcol;
      if (row < (size_t)N) {
        *reinterpret_cast<float2*>(out + row * COUT + col) =
            make_float2(acc[mi][ni][0], acc[mi][ni][1]);
        *reinterpret_cast<float2*>(out + (row + 8) * COUT + col) =
            make_float2(acc[mi][ni][2], acc[mi][ni][3]);
      }
    }
  }
}

}  // namespace

// ───────────────────────────── launch ─────────────────────────────

extern "C" void kernel_launch(void* const* d_in, const int* in_sizes, int n_in,
                              void* d_out, int out_size) {
  const float* q_pts = (const float*)d_in[0];
  const float* s_pts = (const float*)d_in[1];
  const float* x     = (const float*)d_in[2];
  const float* genW  = (const float*)d_in[3];
  const float* genB  = (const float*)d_in[4];
  const float* wts   = (const float*)d_in[5];
  const int*   inds  = (const int*)d_in[6];
  float* out = (float*)d_out;

  int N  = in_sizes[0] / 3;
  const int Ns = in_sizes[1] / 3;
  if (N > MAXN) N = MAXN;

  cudaFuncSetAttribute(gemm_kernel,
                       cudaFuncAttributeMaxDynamicSharedMemorySize, GSMEM);

  const int grid1 = (N + TILE - 1) / TILE;
  producer_kernel<<<grid1, NT>>>(q_pts, s_pts, x, genW, genB, wts, inds, N, Ns);

  const int grid3 = (N + 127) / 128;
  gemm_kernel<<<grid3, 256, GSMEM>>>(out, N);
}

// round 6
// speedup vs baseline: 2.9803x; 1.5238x over previous
#include <cuda_runtime.h>
#include <cuda_fp16.h>
#include <cstdint>

// ─────────────────────────────────────────────────────────────────────────────
// KPConv: producer (gather + kernel-point weights + MLP-batched phase-4
// reduction, packed fp32 FFMA2) writes weighted features as fp16; mma.sync
// fp16 HMMA GEMM (single-term: fp16 quantization error ~2.5e-4 << 1e-3
// threshold) computes out = weighted @ W with fp32 accumulators.
// tcgen05 unavailable (harness PTX target is sm_103, not sm_103a).
// ─────────────────────────────────────────────────────────────────────────────

namespace {

typedef unsigned long long u64;

constexpr int H    = 26;
constexpr int PADH = 28;
constexpr int KP   = 10;
constexpr int CIN  = 64;
constexpr int COUT = 128;
constexpr int KDIM = KP * CIN;   // 640
constexpr int TILE = 32;
constexpr int NT   = 256;
constexpr float INV_EXT = 1.0f / 1.2f;
constexpr int MAXN = 65536;

// Scratch (device-global: no allocation allowed in kernel_launch).
__device__ __half g_A[(size_t)MAXN * KDIM];
__device__ __half g_B[(size_t)COUT * KDIM];   // [o][k*64+i]

__device__ __forceinline__ uint32_t smem_u32(const void* p) {
  uint32_t a;
  asm("{ .reg .u64 t; cvta.to.shared.u64 t, %1; cvt.u32.u64 %0, t; }"
      : "=r"(a) : "l"(p));
  return a;
}

// Packed 2xfp32 ops (sm_100+ base PTX).
__device__ __forceinline__ u64 ffma2(u64 a, u64 b, u64 c) {
  u64 d;
  asm("fma.rn.f32x2 %0, %1, %2, %3;" : "=l"(d) : "l"(a), "l"(b), "l"(c));
  return d;
}
__device__ __forceinline__ u64 pack2(float lo, float hi) {
  u64 d;
  asm("mov.b64 %0, {%1, %2};" : "=l"(d) : "f"(lo), "f"(hi));
  return d;
}
__device__ __forceinline__ float2 unpack2(u64 v) {
  float2 r;
  asm("mov.b64 {%0, %1}, %2;" : "=f"(r.x), "=f"(r.y) : "l"(v));
  return r;
}

// ───────────────────── Kernel 1: producer (+ folded B prep) ─────────────────────

struct P1Smem {
  u64   genWT2[42 * 32];       // [m2][j]: packed (W[2m2][j], W[2m2+1][j])
  float genB[32];
  float sP[8][84];
  float sKP[8][32];
  alignas(16) float swv[8][H * 12];  // [h][k]
  int   sIdx[8][H];
};

constexpr int PREPB = 64;      // blocks that also transpose W -> fp16

__global__ void __launch_bounds__(NT, 3)
producer_kernel(const float* __restrict__ q_pts,
                const float* __restrict__ s_pts,
                const float* __restrict__ x,
                const float* __restrict__ genW,
                const float* __restrict__ genB,
                const float* __restrict__ weights,
                const int*   __restrict__ inds,
                int N, int Ns)
{
  __shared__ P1Smem sm;
  const int tid  = threadIdx.x;
  const int lane = tid & 31;
  const int wid  = tid >> 5;

  // Folded B prep: first PREPB blocks transpose W to fp16 (write-coalesced).
  if (blockIdx.x < PREPB) {
    for (int t = blockIdx.x * NT + tid; t < KDIM * COUT; t += PREPB * NT) {
      const int o  = t / KDIM;
      const int ki = t - o * KDIM;
      g_B[t] = __float2half_rn(weights[(size_t)ki * COUT + o]);
    }
  }

  // Stage gen_W as packed m-pairs.
  for (int t = tid; t < 42 * 32; t += NT) {
    const int j  = t & 31;
    const int m2 = t >> 5;
    if (j < 30)
      sm.genWT2[t] = pack2(genW[j * 84 + 2 * m2], genW[j * 84 + 2 * m2 + 1]);
    else
      sm.genWT2[t] = 0;
  }
  if (tid < 30) sm.genB[tid] = genB[tid];
  __syncthreads();

  const int n_base = blockIdx.x * TILE;

  for (int it = 0; it < TILE / 8; ++it) {
    const int p = wid * (TILE / 8) + it;
    const int n = n_base + p;
    if (n < N) {
      const float qx = q_pts[3 * n + 0];
      const float qy = q_pts[3 * n + 1];
      const float qz = q_pts[3 * n + 2];

      // Phase 1: neighbor gather into padded 84-vector.
      if (lane < H) {
        int j = inds[(size_t)n * H + lane];
        float sx, sy, sz;
        if (j >= 0 && j < Ns) {
          sx = s_pts[3 * j + 0];
          sy = s_pts[3 * j + 1];
          sz = s_pts[3 * j + 2];
        } else {
          sx = sy = sz = 1e6f;   // shadow point -> zero influence
          j = 0;
        }
        sm.sP[wid][lane * 3 + 0] = sx - qx;
        sm.sP[wid][lane * 3 + 1] = sy - qy;
        sm.sP[wid][lane * 3 + 2] = sz - qz;
        sm.sIdx[wid][lane] = j;
      } else if (lane < PADH) {
        const int b = lane - H;
        sm.sP[wid][78 + b * 3 + 0] = -1.0f;
        sm.sP[wid][78 + b * 3 + 1] = -1.0f;
        sm.sP[wid][78 + b * 3 + 2] = -1.0f;
      }
      __syncwarp();

      // Phase 2: kp = gen_W @ p + gen_b, packed 2-wide over m.
      if (lane < 30) {
        u64 acc2 = 0;
        const u64* pp = reinterpret_cast<const u64*>(&sm.sP[wid][0]);
        #pragma unroll 6
        for (int m2 = 0; m2 < 42; ++m2)
          acc2 = ffma2(sm.genWT2[m2 * 32 + lane], pp[m2], acc2);
        const float2 r = unpack2(acc2);
        sm.sKP[wid][lane] = r.x + r.y + sm.genB[lane];
      }
      __syncwarp();

      // Phase 3: influence weights w[h][k] = relu(1 - ||nbr - kp|| / ext).
      for (int t = lane; t < KP * H; t += 32) {
        const int k = t / H;
        const int h = t - k * H;
        const float dx = sm.sP[wid][h * 3 + 0] - sm.sKP[wid][k * 3 + 0];
        const float dy = sm.sP[wid][h * 3 + 1] - sm.sKP[wid][k * 3 + 1];
        const float dz = sm.sP[wid][h * 3 + 2] - sm.sKP[wid][k * 3 + 2];
        const float d  = sqrtf(fmaf(dx, dx, fmaf(dy, dy, dz * dz)));
        sm.swv[wid][h * 12 + k] = fmaxf(1.0f - d * INV_EXT, 0.0f);
      }
      __syncwarp();

      // Phase 4: weighted[k][c] = sum_h w[k][h] * x[idx[h]][c].
      // MLP batching: 2 halves of 13 independent gathers in flight.
      u64 acc2[5][2];
      #pragma unroll
      for (int kk = 0; kk < 5; ++kk) { acc2[kk][0] = 0; acc2[kk][1] = 0; }

      #pragma unroll
      for (int half = 0; half < 2; ++half) {
        const int hb = half * 13;
        float2 xb[13];
        #pragma unroll
        for (int hh = 0; hh < 13; ++hh) {
          const int jn = sm.sIdx[wid][hb + hh];
          xb[hh] = *reinterpret_cast<const float2*>(
              x + (size_t)jn * CIN + 2 * lane);
        }
        #pragma unroll
        for (int hh = 0; hh < 13; ++hh) {
          const u64 x0 = pack2(xb[hh].x, xb[hh].x);
          const u64 x1 = pack2(xb[hh].y, xb[hh].y);
          const u64* wp =
              reinterpret_cast<const u64*>(&sm.swv[wid][(hb + hh) * 12]);
          #pragma unroll
          for (int kk = 0; kk < 5; ++kk) {
            const u64 w2 = wp[kk];
            acc2[kk][0] = ffma2(w2, x0, acc2[kk][0]);
            acc2[kk][1] = ffma2(w2, x1, acc2[kk][1]);
          }
        }
      }

      // Store as fp16.
      #pragma unroll
      for (int kk = 0; kk < 5; ++kk) {
        const float2 a0 = unpack2(acc2[kk][0]);   // col c0: (k even, k odd)
        const float2 a1 = unpack2(acc2[kk][1]);   // col c1
        const size_t off0 = (size_t)n * KDIM + (2 * kk) * CIN + 2 * lane;
        const size_t off1 = (size_t)n * KDIM + (2 * kk + 1) * CIN + 2 * lane;
        *reinterpret_cast<__half2*>(g_A + off0) =
            __floats2half2_rn(a0.x, a1.x);
        *reinterpret_cast<__half2*>(g_A + off1) =
            __floats2half2_rn(a0.y, a1.y);
      }
    }
    __syncwarp();
  }
}

// ───────────────────── Kernel 2: fp16 mma.sync GEMM out = A @ B^T ───────────────
// CTA: 128 rows x 128 cols, 8 warps 2x4, warp tile 64x32. 20 K-tiles of 32,
// 4-stage cp.async ring (A,B fp16 tiles only), one __syncthreads per tile.
// 80B smem pitch (conflict-free ldmatrix). 2 CTAs/SM for latency hiding.

constexpr int KT      = 32;
constexpr int PITCH   = 80;
constexpr int TSZ     = 128 * PITCH;       // 10240 B
constexpr int STAGE   = 2 * TSZ;           // A + B = 20480 B
constexpr int NSTAGES = 4;
constexpr int GSMEM   = NSTAGES * STAGE;   // 81920 B  (2 CTAs -> 160 KB/SM)
constexpr int NKT     = KDIM / KT;         // 20

__device__ __forceinline__ void cp16(uint32_t dst, const void* src) {
  asm volatile("cp.async.cg.shared.global [%0], [%1], 16;"
               :: "r"(dst), "l"(src) : "memory");
}
__device__ __forceinline__ void cp_commit() {
  asm volatile("cp.async.commit_group;" ::: "memory");
}
__device__ __forceinline__ void cp_wait2() {
  asm volatile("cp.async.wait_group 2;" ::: "memory");
}

__device__ __forceinline__ void ldm4(uint32_t* r, uint32_t addr) {
  asm volatile("ldmatrix.sync.aligned.m8n8.x4.shared.b16 {%0,%1,%2,%3}, [%4];"
               : "=r"(r[0]), "=r"(r[1]), "=r"(r[2]), "=r"(r[3]) : "r"(addr));
}

__device__ __forceinline__ void mma16816(float* d, const uint32_t* a,
                                         const uint32_t* b) {
  asm volatile(
      "mma.sync.aligned.m16n8k16.row.col.f32.f16.f16.f32 "
      "{%0,%1,%2,%3}, {%4,%5,%6,%7}, {%8,%9}, {%0,%1,%2,%3};"
      : "+f"(d[0]), "+f"(d[1]), "+f"(d[2]), "+f"(d[3])
      : "r"(a[0]), "r"(a[1]), "r"(a[2]), "r"(a[3]), "r"(b[0]), "r"(b[1]));
}

__global__ void __launch_bounds__(256, 2)
gemm_kernel(float* __restrict__ out, int N)
{
  extern __shared__ char sm[];
  const uint32_t sb = smem_u32(sm);
  const int tid  = threadIdx.x;
  const int lane = tid & 31;
  const int wid  = tid >> 5;
  const int wr   = wid >> 2;
  const int wc   = wid & 3;
  const size_t n0 = (size_t)blockIdx.x * 128;

  // cp.async mapping: tile = 128 rows x 4 chunks of 16B = 512 chunks,
  // 2 per thread per tile.
  const int id0 = tid, id1 = tid + 256;
  const int r0 = id0 >> 2, c0 = id0 & 3;
  const int r1 = id1 >> 2, c1 = id1 & 3;

  auto load_stage = [&](int st, int kc) {
    const uint32_t base = sb + st * STAGE;
    const size_t ga0 = (n0 + r0) * KDIM + kc * KT + c0 * 8;
    const size_t ga1 = (n0 + r1) * KDIM + kc * KT + c1 * 8;
    const size_t gb0 = (size_t)r0 * KDIM + kc * KT + c0 * 8;
    const size_t gb1 = (size_t)r1 * KDIM + kc * KT + c1 * 8;
    const uint32_t d0 = r0 * PITCH + c0 * 16;
    const uint32_t d1 = r1 * PITCH + c1 * 16;
    cp16(base + 0 * TSZ + d0, g_A + ga0);
    cp16(base + 0 * TSZ + d1, g_A + ga1);
    cp16(base + 1 * TSZ + d0, g_B + gb0);
    cp16(base + 1 * TSZ + d1, g_B + gb1);
  };

  load_stage(0, 0); cp_commit();
  load_stage(1, 1); cp_commit();
  load_stage(2, 2); cp_commit();

  const int arow  = lane & 15;
  const int acolB = (lane >> 4) * 16;
  const int brow  = (lane & 7) + ((lane >> 4) << 3);
  const int bcolB = ((lane >> 3) & 1) * 16;

  float acc[4][4][4];
  #pragma unroll
  for (int mi = 0; mi < 4; ++mi)
    #pragma unroll
    for (int ni = 0; ni < 4; ++ni)
      #pragma unroll
      for (int j = 0; j < 4; ++j) acc[mi][ni][j] = 0.f;

  for (int kc = 0; kc < NKT; ++kc) {
    const int st = kc & (NSTAGES - 1);
    cp_wait2();          // stage kc resident
    __syncthreads();     // all warps done with the slot we overwrite below

    if (kc + 3 < NKT) load_stage((kc + 3) & (NSTAGES - 1), kc + 3);
    cp_commit();

    const uint32_t tA = sb + st * STAGE + 0 * TSZ;
    const uint32_t tB = sb + st * STAGE + 1 * TSZ;

    #pragma unroll
    for (int ks = 0; ks < 2; ++ks) {
      uint32_t ah[4][4], bh[4][2];
      #pragma unroll
      for (int mi = 0; mi < 4; ++mi) {
        const uint32_t ao = (wr * 64 + mi * 16 + arow) * PITCH + ks * 32 + acolB;
        ldm4(ah[mi], tA + ao);
      }
      #pragma unroll
      for (int bi = 0; bi < 2; ++bi) {
        const uint32_t bo = (wc * 32 + bi * 16 + brow) * PITCH + ks * 32 + bcolB;
        uint32_t t4[4];
        ldm4(t4, tB + bo);
        bh[2 * bi][0] = t4[0]; bh[2 * bi][1] = t4[1];
        bh[2 * bi + 1][0] = t4[2]; bh[2 * bi + 1][1] = t4[3];
      }
      #pragma unroll
      for (int mi = 0; mi < 4; ++mi)
        #pragma unroll
        for (int ni = 0; ni < 4; ++ni)
          mma16816(acc[mi][ni], ah[mi], bh[ni]);
    }
  }

  const int trow = lane >> 2;
  const int tcol = (lane & 3) * 2;
  #pragma unroll
  for (int mi = 0; mi < 4; ++mi) {
    const size_t row = n0 + wr * 64 + mi * 16 + trow;
    #pragma unroll
    for (int ni = 0; ni < 4; ++ni) {
      const int col = wc * 32 + ni * 8 + tcol;
      if (row < (size_t)N) {
        *reinterpret_cast<float2*>(out + row * COUT + col) =
            make_float2(acc[mi][ni][0], acc[mi][ni][1]);
        *reinterpret_cast<float2*>(out + (row + 8) * COUT + col) =
            make_float2(acc[mi][ni][2], acc[mi][ni][3]);
      }
    }
  }
}

}  // namespace

// ───────────────────────────── launch ─────────────────────────────

extern "C" void kernel_launch(void* const* d_in, const int* in_sizes, int n_in,
                              void* d_out, int out_size) {
  const float* q_pts = (const float*)d_in[0];
  const float* s_pts = (const float*)d_in[1];
  const float* x     = (const float*)d_in[2];
  const float* genW  = (const float*)d_in[3];
  const float* genB  = (const float*)d_in[4];
  const float* wts   = (const float*)d_in[5];
  const int*   inds  = (const int*)d_in[6];
  float* out = (float*)d_out;

  int N  = in_sizes[0] / 3;
  const int Ns = in_sizes[1] / 3;
  if (N > MAXN) N = MAXN;

  cudaFuncSetAttribute(gemm_kernel,
                       cudaFuncAttributeMaxDynamicSharedMemorySize, GSMEM);

  const int grid1 = (N + TILE - 1) / TILE;
  producer_kernel<<<grid1, NT>>>(q_pts, s_pts, x, genW, genB, wts, inds, N, Ns);

  const int grid3 = (N + 127) / 128;
  gemm_kernel<<<grid3, 256, GSMEM>>>(out, N);
}

// round 7
// speedup vs baseline: 3.0180x; 1.0126x over previous
#include <cuda_runtime.h>
#include <cuda_fp16.h>
#include <cstdint>

// ─────────────────────────────────────────────────────────────────────────────
// KPConv: prep (x→fp16, W transpose→fp16) ➜ producer (gather + kernel-point
// weights + MLP-batched phase-4, fp32 FFMA2 accum) ➜ fp16 HMMA GEMM with
// 64x64 warp tiles. tcgen05 unavailable (harness targets sm_103, not sm_103a).
// ─────────────────────────────────────────────────────────────────────────────

namespace {

typedef unsigned long long u64;

constexpr int H    = 26;
constexpr int PADH = 28;
constexpr int KP   = 10;
constexpr int CIN  = 64;
constexpr int COUT = 128;
constexpr int KDIM = KP * CIN;   // 640
constexpr int TILE = 32;
constexpr int NT   = 256;
constexpr float INV_EXT = 1.0f / 1.2f;
constexpr int MAXN = 65536;

// Scratch (device-global: no allocation allowed in kernel_launch).
__device__ __half g_A[(size_t)MAXN * KDIM];
__device__ __half g_B[(size_t)COUT * KDIM];   // [o][k*64+i]
__device__ __half g_X[(size_t)MAXN * CIN];    // fp16 copy of x

__device__ __forceinline__ uint32_t smem_u32(const void* p) {
  uint32_t a;
  asm("{ .reg .u64 t; cvta.to.shared.u64 t, %1; cvt.u32.u64 %0, t; }"
      : "=r"(a) : "l"(p));
  return a;
}

// Packed 2xfp32 ops (sm_100+ base PTX).
__device__ __forceinline__ u64 ffma2(u64 a, u64 b, u64 c) {
  u64 d;
  asm("fma.rn.f32x2 %0, %1, %2, %3;" : "=l"(d) : "l"(a), "l"(b), "l"(c));
  return d;
}
__device__ __forceinline__ u64 pack2(float lo, float hi) {
  u64 d;
  asm("mov.b64 %0, {%1, %2};" : "=l"(d) : "f"(lo), "f"(hi));
  return d;
}
__device__ __forceinline__ float2 unpack2(u64 v) {
  float2 r;
  asm("mov.b64 {%0, %1}, %2;" : "=f"(r.x), "=f"(r.y) : "l"(v));
  return r;
}

// ───────────────────── Kernel 0: prep (x→fp16, W→fp16 transposed) ───────────────

__global__ void prep_kernel(const float* __restrict__ x,
                            const float* __restrict__ weights,
                            int total_x)
{
  const int gid    = blockIdx.x * blockDim.x + threadIdx.x;
  const int stride = gridDim.x * blockDim.x;

  // x conversion (vectorized float4 -> half2 x2).
  const int nv = total_x / 4;
  const float4* xv = reinterpret_cast<const float4*>(x);
  for (int i = gid; i < nv; i += stride) {
    const float4 v = xv[i];
    __half2* dst = reinterpret_cast<__half2*>(g_X + (size_t)i * 4);
    dst[0] = __floats2half2_rn(v.x, v.y);
    dst[1] = __floats2half2_rn(v.z, v.w);
  }

  // W transpose + convert: g_B[o][ki] = W[ki][o].
  for (int t = gid; t < KDIM * COUT; t += stride) {
    const int o  = t / KDIM;
    const int ki = t - o * KDIM;
    g_B[t] = __float2half_rn(weights[(size_t)ki * COUT + o]);
  }
}

// ───────────────────── Kernel 1: weighted-feature producer ─────────────────────

struct P1Smem {
  u64   genWT2[42 * 32];       // [m2][j]: packed (W[2m2][j], W[2m2+1][j])
  float genB[32];
  float sP[8][84];
  float sKP[8][32];
  alignas(16) float swv[8][H * 12];  // [h][k]
  int   sIdx[8][H];
};

__global__ void __launch_bounds__(NT, 4)
producer_kernel(const float* __restrict__ q_pts,
                const float* __restrict__ s_pts,
                const float* __restrict__ genW,
                const float* __restrict__ genB,
                const int*   __restrict__ inds,
                int N, int Ns)
{
  __shared__ P1Smem sm;
  const int tid  = threadIdx.x;
  const int lane = tid & 31;
  const int wid  = tid >> 5;

  // Stage gen_W as packed m-pairs.
  for (int t = tid; t < 42 * 32; t += NT) {
    const int j  = t & 31;
    const int m2 = t >> 5;
    if (j < 30)
      sm.genWT2[t] = pack2(genW[j * 84 + 2 * m2], genW[j * 84 + 2 * m2 + 1]);
    else
      sm.genWT2[t] = 0;
  }
  if (tid < 30) sm.genB[tid] = genB[tid];
  __syncthreads();

  const int n_base = blockIdx.x * TILE;

  for (int it = 0; it < TILE / 8; ++it) {
    const int p = wid * (TILE / 8) + it;
    const int n = n_base + p;
    if (n < N) {
      const float qx = q_pts[3 * n + 0];
      const float qy = q_pts[3 * n + 1];
      const float qz = q_pts[3 * n + 2];

      // Phase 1: neighbor gather into padded 84-vector.
      if (lane < H) {
        int j = inds[(size_t)n * H + lane];
        float sx, sy, sz;
        if (j >= 0 && j < Ns) {
          sx = s_pts[3 * j + 0];
          sy = s_pts[3 * j + 1];
          sz = s_pts[3 * j + 2];
        } else {
          sx = sy = sz = 1e6f;   // shadow point -> zero influence
          j = 0;
        }
        sm.sP[wid][lane * 3 + 0] = sx - qx;
        sm.sP[wid][lane * 3 + 1] = sy - qy;
        sm.sP[wid][lane * 3 + 2] = sz - qz;
        sm.sIdx[wid][lane] = j;
      } else if (lane < PADH) {
        const int b = lane - H;
        sm.sP[wid][78 + b * 3 + 0] = -1.0f;
        sm.sP[wid][78 + b * 3 + 1] = -1.0f;
        sm.sP[wid][78 + b * 3 + 2] = -1.0f;
      }
      __syncwarp();

      // Phase 2: kp = gen_W @ p + gen_b; two independent FFMA2 chains.
      if (lane < 30) {
        u64 accA = 0, accB = 0;
        const u64* pp = reinterpret_cast<const u64*>(&sm.sP[wid][0]);
        #pragma unroll
        for (int m2 = 0; m2 < 21; ++m2) {
          accA = ffma2(sm.genWT2[m2 * 32 + lane], pp[m2], accA);
          accB = ffma2(sm.genWT2[(m2 + 21) * 32 + lane], pp[m2 + 21], accB);
        }
        const float2 ra = unpack2(accA);
        const float2 rb = unpack2(accB);
        sm.sKP[wid][lane] = (ra.x + ra.y) + (rb.x + rb.y) + sm.genB[lane];
      }
      __syncwarp();

      // Phase 3: influence weights w[h][k] = relu(1 - ||nbr - kp|| / ext).
      for (int t = lane; t < KP * H; t += 32) {
        const int k = t / H;
        const int h = t - k * H;
        const float dx = sm.sP[wid][h * 3 + 0] - sm.sKP[wid][k * 3 + 0];
        const float dy = sm.sP[wid][h * 3 + 1] - sm.sKP[wid][k * 3 + 1];
        const float dz = sm.sP[wid][h * 3 + 2] - sm.sKP[wid][k * 3 + 2];
        const float d  = sqrtf(fmaf(dx, dx, fmaf(dy, dy, dz * dz)));
        sm.swv[wid][h * 12 + k] = fmaxf(1.0f - d * INV_EXT, 0.0f);
      }
      __syncwarp();

      // Phase 4: weighted[k][c] = sum_h w[k][h] * x[idx[h]][c].
      // fp16 gathers (one 128B line per row), fp32 FFMA2 accumulation.
      u64 acc2[5][2];
      #pragma unroll
      for (int kk = 0; kk < 5; ++kk) { acc2[kk][0] = 0; acc2[kk][1] = 0; }

      #pragma unroll
      for (int half = 0; half < 2; ++half) {
        const int hb = half * 13;
        __half2 xb[13];
        #pragma unroll
        for (int hh = 0; hh < 13; ++hh) {
          const int jn = sm.sIdx[wid][hb + hh];
          xb[hh] = *reinterpret_cast<const __half2*>(
              g_X + (size_t)jn * CIN + 2 * lane);
        }
        #pragma unroll
        for (int hh = 0; hh < 13; ++hh) {
          const float2 xv = __half22float2(xb[hh]);
          const u64 x0 = pack2(xv.x, xv.x);
          const u64 x1 = pack2(xv.y, xv.y);
          const u64* wp =
              reinterpret_cast<const u64*>(&sm.swv[wid][(hb + hh) * 12]);
          #pragma unroll
          for (int kk = 0; kk < 5; ++kk) {
            const u64 w2 = wp[kk];
            acc2[kk][0] = ffma2(w2, x0, acc2[kk][0]);
            acc2[kk][1] = ffma2(w2, x1, acc2[kk][1]);
          }
        }
      }

      // Store as fp16.
      #pragma unroll
      for (int kk = 0; kk < 5; ++kk) {
        const float2 a0 = unpack2(acc2[kk][0]);   // col c0: (k even, k odd)
        const float2 a1 = unpack2(acc2[kk][1]);   // col c1
        const size_t off0 = (size_t)n * KDIM + (2 * kk) * CIN + 2 * lane;
        const size_t off1 = (size_t)n * KDIM + (2 * kk + 1) * CIN + 2 * lane;
        *reinterpret_cast<__half2*>(g_A + off0) = __floats2half2_rn(a0.x, a1.x);
        *reinterpret_cast<__half2*>(g_A + off1) = __floats2half2_rn(a0.y, a1.y);
      }
    }
    __syncwarp();
  }
}

// ───────────────────── Kernel 2: fp16 mma.sync GEMM out = A @ B^T ───────────────
// CTA 128x128, 4 warps in 2x2 grid of 64x64 warp tiles (16 MAC/B of LDS —
// tensor-bound, not smem-bound). 20 K-tiles of 32, 4-stage cp.async ring.
// 80B pitch (conflict-free ldmatrix). 2 CTAs/SM.

constexpr int KT      = 32;
constexpr int PITCH   = 80;
constexpr int TSZ     = 128 * PITCH;       // 10240 B
constexpr int STAGE   = 2 * TSZ;           // A + B = 20480 B
constexpr int NSTAGES = 4;
constexpr int GSMEM   = NSTAGES * STAGE;   // 81920 B
constexpr int NKT     = KDIM / KT;         // 20
constexpr int GNT     = 128;               // 4 warps

__device__ __forceinline__ void cp16(uint32_t dst, const void* src) {
  asm volatile("cp.async.cg.shared.global [%0], [%1], 16;"
               :: "r"(dst), "l"(src) : "memory");
}
__device__ __forceinline__ void cp_commit() {
  asm volatile("cp.async.commit_group;" ::: "memory");
}
__device__ __forceinline__ void cp_wait2() {
  asm volatile("cp.async.wait_group 2;" ::: "memory");
}

__device__ __forceinline__ void ldm4(uint32_t* r, uint32_t addr) {
  asm volatile("ldmatrix.sync.aligned.m8n8.x4.shared.b16 {%0,%1,%2,%3}, [%4];"
               : "=r"(r[0]), "=r"(r[1]), "=r"(r[2]), "=r"(r[3]) : "r"(addr));
}

__device__ __forceinline__ void mma16816(float* d, const uint32_t* a,
                                         const uint32_t* b) {
  asm volatile(
      "mma.sync.aligned.m16n8k16.row.col.f32.f16.f16.f32 "
      "{%0,%1,%2,%3}, {%4,%5,%6,%7}, {%8,%9}, {%0,%1,%2,%3};"
      : "+f"(d[0]), "+f"(d[1]), "+f"(d[2]), "+f"(d[3])
      : "r"(a[0]), "r"(a[1]), "r"(a[2]), "r"(a[3]), "r"(b[0]), "r"(b[1]));
}

__global__ void __launch_bounds__(GNT, 2)
gemm_kernel(float* __restrict__ out, int N)
{
  extern __shared__ char sm[];
  const uint32_t sb = smem_u32(sm);
  const int tid  = threadIdx.x;
  const int lane = tid & 31;
  const int wid  = tid >> 5;
  const int wr   = wid >> 1;       // 0..1 -> rows wr*64
  const int wc   = wid & 1;        // 0..1 -> cols wc*64
  const size_t n0 = (size_t)blockIdx.x * 128;

  // cp.async mapping: tile = 128 rows x 4 chunks of 16B = 512 chunks,
  // 4 per thread per tile.
  auto load_stage = [&](int st, int kc) {
    const uint32_t base = sb + st * STAGE;
    #pragma unroll
    for (int i = 0; i < 4; ++i) {
      const int id = tid + i * GNT;
      const int r  = id >> 2;
      const int c  = id & 3;
      const uint32_t d = r * PITCH + c * 16;
      cp16(base + 0 * TSZ + d, g_A + (n0 + r) * KDIM + kc * KT + c * 8);
      cp16(base + 1 * TSZ + d, g_B + (size_t)r * KDIM + kc * KT + c * 8);
    }
  };

  load_stage(0, 0); cp_commit();
  load_stage(1, 1); cp_commit();
  load_stage(2, 2); cp_commit();

  const int arow  = lane & 15;
  const int acolB = (lane >> 4) * 16;
  const int brow  = (lane & 7) + ((lane >> 4) << 3);
  const int bcolB = ((lane >> 3) & 1) * 16;

  float acc[4][8][4];
  #pragma unroll
  for (int mi = 0; mi < 4; ++mi)
    #pragma unroll
    for (int ni = 0; ni < 8; ++ni)
      #pragma unroll
      for (int j = 0; j < 4; ++j) acc[mi][ni][j] = 0.f;

  for (int kc = 0; kc < NKT; ++kc) {
    const int st = kc & (NSTAGES - 1);
    cp_wait2();          // stage kc resident
    __syncthreads();     // all warps done with the slot we overwrite below

    if (kc + 3 < NKT) load_stage((kc + 3) & (NSTAGES - 1), kc + 3);
    cp_commit();

    const uint32_t tA = sb + st * STAGE + 0 * TSZ;
    const uint32_t tB = sb + st * STAGE + 1 * TSZ;

    #pragma unroll
    for (int ks = 0; ks < 2; ++ks) {
      uint32_t ah[4][4], bh[8][2];
      #pragma unroll
      for (int mi = 0; mi < 4; ++mi) {
        const uint32_t ao = (wr * 64 + mi * 16 + arow) * PITCH + ks * 32 + acolB;
        ldm4(ah[mi], tA + ao);
      }
      #pragma unroll
      for (int bi = 0; bi < 4; ++bi) {
        const uint32_t bo = (wc * 64 + bi * 16 + brow) * PITCH + ks * 32 + bcolB;
        uint32_t t4[4];
        ldm4(t4, tB + bo);
        bh[2 * bi][0] = t4[0]; bh[2 * bi][1] = t4[1];
        bh[2 * bi + 1][0] = t4[2]; bh[2 * bi + 1][1] = t4[3];
      }
      #pragma unroll
      for (int mi = 0; mi < 4; ++mi)
        #pragma unroll
        for (int ni = 0; ni < 8; ++ni)
          mma16816(acc[mi][ni], ah[mi], bh[ni]);
    }
  }

  const int trow = lane >> 2;
  const int tcol = (lane & 3) * 2;
  #pragma unroll
  for (int mi = 0; mi < 4; ++mi) {
    const size_t row = n0 + wr * 64 + mi * 16 + trow;
    #pragma unroll
    for (int ni = 0; ni < 8; ++ni) {
      const int col = wc * 64 + ni * 8 + tcol;
      if (row < (size_t)N) {
        *reinterpret_cast<float2*>(out + row * COUT + col) =
            make_float2(acc[mi][ni][0], acc[mi][ni][1]);
        *reinterpret_cast<float2*>(out + (row + 8) * COUT + col) =
            make_float2(acc[mi][ni][2], acc[mi][ni][3]);
      }
    }
  }
}

}  // namespace

// ───────────────────────────── launch ─────────────────────────────

extern "C" void kernel_launch(void* const* d_in, const int* in_sizes, int n_in,
                              void* d_out, int out_size) {
  const float* q_pts = (const float*)d_in[0];
  const float* s_pts = (const float*)d_in[1];
  const float* x     = (const float*)d_in[2];
  const float* genW  = (const float*)d_in[3];
  const float* genB  = (const float*)d_in[4];
  const float* wts   = (const float*)d_in[5];
  const int*   inds  = (const int*)d_in[6];
  float* out = (float*)d_out;

  int N  = in_sizes[0] / 3;
  const int Ns = in_sizes[1] / 3;
  if (N > MAXN) N = MAXN;

  cudaFuncSetAttribute(gemm_kernel,
                       cudaFuncAttributeMaxDynamicSharedMemorySize, GSMEM);

  prep_kernel<<<512, 256>>>(x, wts, N * CIN);

  const int grid1 = (N + TILE - 1) / TILE;
  producer_kernel<<<grid1, NT>>>(q_pts, s_pts, genW, genB, inds, N, Ns);

  const int grid3 = (N + 127) / 128;
  gemm_kernel<<<grid3, GNT, GSMEM>>>(out, N);
}

// round 8
// speedup vs baseline: 3.1940x; 1.0583x over previous
#include <cuda_runtime.h>
#include <cuda_fp16.h>
#include <cstdint>

// ─────────────────────────────────────────────────────────────────────────────
// KPConv: prep (x→fp16, W transpose→fp16) ➜ producer (phases 1-2 batched
// across 4 points/warp for cross-point ILP; phase-4 gathers double-buffered
// behind phase-3 weight computation) ➜ fp16 HMMA GEMM, 64x64 warp tiles.
// tcgen05 unavailable (harness targets sm_103, not sm_103a).
// ─────────────────────────────────────────────────────────────────────────────

namespace {

typedef unsigned long long u64;

constexpr int H    = 26;
constexpr int KP   = 10;
constexpr int CIN  = 64;
constexpr int COUT = 128;
constexpr int KDIM = KP * CIN;   // 640
constexpr int TILE = 32;
constexpr int NT   = 256;
constexpr float INV_EXT = 1.0f / 1.2f;
constexpr int MAXN = 65536;

// Scratch (device-global: no allocation allowed in kernel_launch).
__device__ __half g_A[(size_t)MAXN * KDIM];
__device__ __half g_B[(size_t)COUT * KDIM];   // [o][k*64+i]
__device__ __half g_X[(size_t)MAXN * CIN];    // fp16 copy of x

__device__ __forceinline__ uint32_t smem_u32(const void* p) {
  uint32_t a;
  asm("{ .reg .u64 t; cvta.to.shared.u64 t, %1; cvt.u32.u64 %0, t; }"
      : "=r"(a) : "l"(p));
  return a;
}

// Packed 2xfp32 ops (sm_100+ base PTX).
__device__ __forceinline__ u64 ffma2(u64 a, u64 b, u64 c) {
  u64 d;
  asm("fma.rn.f32x2 %0, %1, %2, %3;" : "=l"(d) : "l"(a), "l"(b), "l"(c));
  return d;
}
__device__ __forceinline__ u64 pack2(float lo, float hi) {
  u64 d;
  asm("mov.b64 %0, {%1, %2};" : "=l"(d) : "f"(lo), "f"(hi));
  return d;
}
__device__ __forceinline__ float2 unpack2(u64 v) {
  float2 r;
  asm("mov.b64 {%0, %1}, %2;" : "=f"(r.x), "=f"(r.y) : "l"(v));
  return r;
}

// ───────────────────── Kernel 0: prep (x→fp16, W→fp16 transposed) ───────────────

__global__ void prep_kernel(const float* __restrict__ x,
                            const float* __restrict__ weights,
                            int total_x)
{
  const int gid    = blockIdx.x * blockDim.x + threadIdx.x;
  const int stride = gridDim.x * blockDim.x;

  const int nv = total_x / 4;
  const float4* xv = reinterpret_cast<const float4*>(x);
  for (int i = gid; i < nv; i += stride) {
    const float4 v = xv[i];
    __half2* dst = reinterpret_cast<__half2*>(g_X + (size_t)i * 4);
    dst[0] = __floats2half2_rn(v.x, v.y);
    dst[1] = __floats2half2_rn(v.z, v.w);
  }

  for (int t = gid; t < KDIM * COUT; t += stride) {
    const int o  = t / KDIM;
    const int ki = t - o * KDIM;
    g_B[t] = __float2half_rn(weights[(size_t)ki * COUT + o]);
  }
}

// ───────────────────── Kernel 1: weighted-feature producer ─────────────────────
// One block = 32 points; each warp owns 4 points. Phases 1-2 batched across
// the warp's 4 points (one latency exposure); phases 3-4 per point with
// gathers double-buffered behind the weight computation.

struct P1Smem {
  u64   genWT2[42 * 32];        // [m2][j]: packed (W[2m2][j], W[2m2+1][j])
  float genB[32];
  float sP[8][4][84];           // padded neighbor vectors, 4 points per warp
  float sKP[8][4][32];          // kernel points
  alignas(16) float swv[8][H * 12];  // [h][k] influence weights (1 pt at a time)
  int   sIdx[8][4][H];          // neighbor indices
};

__global__ void __launch_bounds__(NT, 4)
producer_kernel(const float* __restrict__ q_pts,
                const float* __restrict__ s_pts,
                const float* __restrict__ genW,
                const float* __restrict__ genB,
                const int*   __restrict__ inds,
                int N, int Ns)
{
  __shared__ P1Smem sm;
  const int tid  = threadIdx.x;
  const int lane = tid & 31;
  const int wid  = tid >> 5;

  for (int t = tid; t < 42 * 32; t += NT) {
    const int j  = t & 31;
    const int m2 = t >> 5;
    if (j < 30)
      sm.genWT2[t] = pack2(genW[j * 84 + 2 * m2], genW[j * 84 + 2 * m2 + 1]);
    else
      sm.genWT2[t] = 0;
  }
  if (tid < 30) sm.genB[tid] = genB[tid];
  __syncthreads();

  const int nw = blockIdx.x * TILE + wid * 4;   // first point of this warp

  // ── Phase 1 (batched 4 points): 16 index + 12 coord gathers in flight. ──
  if (lane < H) {
    int jj[4];
    #pragma unroll
    for (int p = 0; p < 4; ++p) {
      const int n = nw + p;
      jj[p] = (n < N) ? inds[(size_t)n * H + lane] : 0;
    }
    float cx[4], cy[4], cz[4];
    #pragma unroll
    for (int p = 0; p < 4; ++p) {
      int j = jj[p];
      if (j >= 0 && j < Ns) {
        cx[p] = s_pts[3 * j + 0];
        cy[p] = s_pts[3 * j + 1];
        cz[p] = s_pts[3 * j + 2];
      } else {
        cx[p] = cy[p] = cz[p] = 1e6f;   // shadow point -> zero influence
        jj[p] = 0;
      }
    }
    #pragma unroll
    for (int p = 0; p < 4; ++p) {
      const int n = nw + p;
      if (n < N) {
        const float qx = q_pts[3 * n + 0];
        const float qy = q_pts[3 * n + 1];
        const float qz = q_pts[3 * n + 2];
        sm.sP[wid][p][lane * 3 + 0] = cx[p] - qx;
        sm.sP[wid][p][lane * 3 + 1] = cy[p] - qy;
        sm.sP[wid][p][lane * 3 + 2] = cz[p] - qz;
        sm.sIdx[wid][p][lane] = jj[p];
      }
    }
  } else if (lane < 28) {
    const int b = lane - H;            // 0 or 1 -> pad entries
    #pragma unroll
    for (int p = 0; p < 4; ++p) {
      sm.sP[wid][p][78 + b * 3 + 0] = -1.0f;
      sm.sP[wid][p][78 + b * 3 + 1] = -1.0f;
      sm.sP[wid][p][78 + b * 3 + 2] = -1.0f;
    }
  }
  __syncwarp();

  // ── Phase 2 (batched): kp[p] = gen_W @ p_vec + gen_b; 8 independent chains. ──
  if (lane < 30) {
    u64 aA[4] = {0, 0, 0, 0}, aB[4] = {0, 0, 0, 0};
    const u64* pp0 = reinterpret_cast<const u64*>(&sm.sP[wid][0][0]);
    const u64* pp1 = reinterpret_cast<const u64*>(&sm.sP[wid][1][0]);
    const u64* pp2 = reinterpret_cast<const u64*>(&sm.sP[wid][2][0]);
    const u64* pp3 = reinterpret_cast<const u64*>(&sm.sP[wid][3][0]);
    #pragma unroll 7
    for (int m2 = 0; m2 < 21; ++m2) {
      const u64 wA = sm.genWT2[m2 * 32 + lane];
      const u64 wB = sm.genWT2[(m2 + 21) * 32 + lane];
      aA[0] = ffma2(wA, pp0[m2], aA[0]);  aB[0] = ffma2(wB, pp0[m2 + 21], aB[0]);
      aA[1] = ffma2(wA, pp1[m2], aA[1]);  aB[1] = ffma2(wB, pp1[m2 + 21], aB[1]);
      aA[2] = ffma2(wA, pp2[m2], aA[2]);  aB[2] = ffma2(wB, pp2[m2 + 21], aB[2]);
      aA[3] = ffma2(wA, pp3[m2], aA[3]);  aB[3] = ffma2(wB, pp3[m2 + 21], aB[3]);
    }
    const float gb = sm.genB[lane];
    #pragma unroll
    for (int p = 0; p < 4; ++p) {
      const float2 ra = unpack2(aA[p]);
      const float2 rb = unpack2(aB[p]);
      sm.sKP[wid][p][lane] = (ra.x + ra.y) + (rb.x + rb.y) + gb;
    }
  }
  __syncwarp();

  // ── Phases 3-4, per point. ──
  for (int p = 0; p < 4; ++p) {
    const int n = nw + p;
    if (n >= N) continue;   // warp-uniform

    const int* idx = &sm.sIdx[wid][p][0];

    // Prefetch gather batch 0 (h = 0..8) BEFORE phase 3 (covers LDG latency).
    __half2 xb[9];
    #pragma unroll
    for (int hh = 0; hh < 9; ++hh)
      xb[hh] = *reinterpret_cast<const __half2*>(
          g_X + (size_t)idx[hh] * CIN + 2 * lane);

    __syncwarp();   // prior point's swv reads complete before overwrite

    // Phase 3: w[h][k] = relu(1 - ||nbr - kp|| / ext).
    for (int t = lane; t < KP * H; t += 32) {
      const int k = t / H;
      const int h = t - k * H;
      const float dx = sm.sP[wid][p][h * 3 + 0] - sm.sKP[wid][p][k * 3 + 0];
      const float dy = sm.sP[wid][p][h * 3 + 1] - sm.sKP[wid][p][k * 3 + 1];
      const float dz = sm.sP[wid][p][h * 3 + 2] - sm.sKP[wid][p][k * 3 + 2];
      const float d  = sqrtf(fmaf(dx, dx, fmaf(dy, dy, dz * dz)));
      sm.swv[wid][h * 12 + k] = fmaxf(1.0f - d * INV_EXT, 0.0f);
    }
    __syncwarp();

    u64 acc2[5][2];
    #pragma unroll
    for (int kk = 0; kk < 5; ++kk) { acc2[kk][0] = 0; acc2[kk][1] = 0; }

    auto accum = [&](int h, __half2 xh) {
      const float2 xv = __half22float2(xh);
      const u64 x0 = pack2(xv.x, xv.x);
      const u64 x1 = pack2(xv.y, xv.y);
      const u64* wp = reinterpret_cast<const u64*>(&sm.swv[wid][h * 12]);
      #pragma unroll
      for (int kk = 0; kk < 5; ++kk) {
        const u64 w2 = wp[kk];
        acc2[kk][0] = ffma2(w2, x0, acc2[kk][0]);
        acc2[kk][1] = ffma2(w2, x1, acc2[kk][1]);
      }
    };

    // Batch 1 prefetch (h = 9..17), then accumulate batch 0.
    __half2 xc[9];
    #pragma unroll
    for (int hh = 0; hh < 9; ++hh)
      xc[hh] = *reinterpret_cast<const __half2*>(
          g_X + (size_t)idx[9 + hh] * CIN + 2 * lane);
    #pragma unroll
    for (int hh = 0; hh < 9; ++hh) accum(hh, xb[hh]);

    // Batch 2 prefetch (h = 18..25), then accumulate batch 1, then batch 2.
    #pragma unroll
    for (int hh = 0; hh < 8; ++hh)
      xb[hh] = *reinterpret_cast<const __half2*>(
          g_X + (size_t)idx[18 + hh] * CIN + 2 * lane);
    #pragma unroll
    for (int hh = 0; hh < 9; ++hh) accum(9 + hh, xc[hh]);
    #pragma unroll
    for (int hh = 0; hh < 8; ++hh) accum(18 + hh, xb[hh]);

    // Store as fp16.
    #pragma unroll
    for (int kk = 0; kk < 5; ++kk) {
      const float2 a0 = unpack2(acc2[kk][0]);   // col c0: (k even, k odd)
      const float2 a1 = unpack2(acc2[kk][1]);   // col c1
      const size_t off0 = (size_t)n * KDIM + (2 * kk) * CIN + 2 * lane;
      const size_t off1 = (size_t)n * KDIM + (2 * kk + 1) * CIN + 2 * lane;
      *reinterpret_cast<__half2*>(g_A + off0) = __floats2half2_rn(a0.x, a1.x);
      *reinterpret_cast<__half2*>(g_A + off1) = __floats2half2_rn(a0.y, a1.y);
    }
  }
}

// ───────────────────── Kernel 2: fp16 mma.sync GEMM out = A @ B^T ───────────────
// CTA 128x128, 4 warps in 2x2 grid of 64x64 warp tiles. 20 K-tiles of 32,
// 4-stage cp.async ring. 80B pitch (conflict-free ldmatrix). 2 CTAs/SM.

constexpr int KT      = 32;
constexpr int PITCH   = 80;
constexpr int TSZ     = 128 * PITCH;       // 10240 B
constexpr int STAGE   = 2 * TSZ;           // A + B = 20480 B
constexpr int NSTAGES = 4;
constexpr int GSMEM   = NSTAGES * STAGE;   // 81920 B
constexpr int NKT     = KDIM / KT;         // 20
constexpr int GNT     = 128;               // 4 warps

__device__ __forceinline__ void cp16(uint32_t dst, const void* src) {
  asm volatile("cp.async.cg.shared.global [%0], [%1], 16;"
               :: "r"(dst), "l"(src) : "memory");
}
__device__ __forceinline__ void cp_commit() {
  asm volatile("cp.async.commit_group;" ::: "memory");
}
__device__ __forceinline__ void cp_wait2() {
  asm volatile("cp.async.wait_group 2;" ::: "memory");
}

__device__ __forceinline__ void ldm4(uint32_t* r, uint32_t addr) {
  asm volatile("ldmatrix.sync.aligned.m8n8.x4.shared.b16 {%0,%1,%2,%3}, [%4];"
               : "=r"(r[0]), "=r"(r[1]), "=r"(r[2]), "=r"(r[3]) : "r"(addr));
}

__device__ __forceinline__ void mma16816(float* d, const uint32_t* a,
                                         const uint32_t* b) {
  asm volatile(
      "mma.sync.aligned.m16n8k16.row.col.f32.f16.f16.f32 "
      "{%0,%1,%2,%3}, {%4,%5,%6,%7}, {%8,%9}, {%0,%1,%2,%3};"
      : "+f"(d[0]), "+f"(d[1]), "+f"(d[2]), "+f"(d[3])
      : "r"(a[0]), "r"(a[1]), "r"(a[2]), "r"(a[3]), "r"(b[0]), "r"(b[1]));
}

__global__ void __launch_bounds__(GNT, 2)
gemm_kernel(float* __restrict__ out, int N)
{
  extern __shared__ char sm[];
  const uint32_t sb = smem_u32(sm);
  const int tid  = threadIdx.x;
  const int lane = tid & 31;
  const int wid  = tid >> 5;
  const int wr   = wid >> 1;
  const int wc   = wid & 1;
  const size_t n0 = (size_t)blockIdx.x * 128;

  auto load_stage = [&](int st, int kc) {
    const uint32_t base = sb + st * STAGE;
    #pragma unroll
    for (int i = 0; i < 4; ++i) {
      const int id = tid + i * GNT;
      const int r  = id >> 2;
      const int c  = id & 3;
      const uint32_t d = r * PITCH + c * 16;
      cp16(base + 0 * TSZ + d, g_A + (n0 + r) * KDIM + kc * KT + c * 8);
      cp16(base + 1 * TSZ + d, g_B + (size_t)r * KDIM + kc * KT + c * 8);
    }
  };

  load_stage(0, 0); cp_commit();
  load_stage(1, 1); cp_commit();
  load_stage(2, 2); cp_commit();

  const int arow  = lane & 15;
  const int acolB = (lane >> 4) * 16;
  const int brow  = (lane & 7) + ((lane >> 4) << 3);
  const int bcolB = ((lane >> 3) & 1) * 16;

  float acc[4][8][4];
  #pragma unroll
  for (int mi = 0; mi < 4; ++mi)
    #pragma unroll
    for (int ni = 0; ni < 8; ++ni)
      #pragma unroll
      for (int j = 0; j < 4; ++j) acc[mi][ni][j] = 0.f;

  for (int kc = 0; kc < NKT; ++kc) {
    const int st = kc & (NSTAGES - 1);
    cp_wait2();
    __syncthreads();

    if (kc + 3 < NKT) load_stage((kc + 3) & (NSTAGES - 1), kc + 3);
    cp_commit();

    const uint32_t tA = sb + st * STAGE + 0 * TSZ;
    const uint32_t tB = sb + st * STAGE + 1 * TSZ;

    #pragma unroll
    for (int ks = 0; ks < 2; ++ks) {
      uint32_t ah[4][4], bh[8][2];
      #pragma unroll
      for (int mi = 0; mi < 4; ++mi) {
        const uint32_t ao = (wr * 64 + mi * 16 + arow) * PITCH + ks * 32 + acolB;
        ldm4(ah[mi], tA + ao);
      }
      #pragma unroll
      for (int bi = 0; bi < 4; ++bi) {
        const uint32_t bo = (wc * 64 + bi * 16 + brow) * PITCH + ks * 32 + bcolB;
        uint32_t t4[4];
        ldm4(t4, tB + bo);
        bh[2 * bi][0] = t4[0]; bh[2 * bi][1] = t4[1];
        bh[2 * bi + 1][0] = t4[2]; bh[2 * bi + 1][1] = t4[3];
      }
      #pragma unroll
      for (int mi = 0; mi < 4; ++mi)
        #pragma unroll
        for (int ni = 0; ni < 8; ++ni)
          mma16816(acc[mi][ni], ah[mi], bh[ni]);
    }
  }

  const int trow = lane >> 2;
  const int tcol = (lane & 3) * 2;
  #pragma unroll
  for (int mi = 0; mi < 4; ++mi) {
    const size_t row = n0 + wr * 64 + mi * 16 + trow;
    #pragma unroll
    for (int ni = 0; ni < 8; ++ni) {
      const int col = wc * 64 + ni * 8 + tcol;
      if (row < (size_t)N) {
        *reinterpret_cast<float2*>(out + row * COUT + col) =
            make_float2(acc[mi][ni][0], acc[mi][ni][1]);
        *reinterpret_cast<float2*>(out + (row + 8) * COUT + col) =
            make_float2(acc[mi][ni][2], acc[mi][ni][3]);
      }
    }
  }
}

}  // namespace

// ───────────────────────────── launch ─────────────────────────────

extern "C" void kernel_launch(void* const* d_in, const int* in_sizes, int n_in,
                              void* d_out, int out_size) {
  const float* q_pts = (const float*)d_in[0];
  const float* s_pts = (const float*)d_in[1];
  const float* x     = (const float*)d_in[2];
  const float* genW  = (const float*)d_in[3];
  const float* genB  = (const float*)d_in[4];
  const float* wts   = (const float*)d_in[5];
  const int*   inds  = (const int*)d_in[6];
  float* out = (float*)d_out;

  int N  = in_sizes[0] / 3;
  const int Ns = in_sizes[1] / 3;
  if (N > MAXN) N = MAXN;

  cudaFuncSetAttribute(gemm_kernel,
                       cudaFuncAttributeMaxDynamicSharedMemorySize, GSMEM);

  prep_kernel<<<1024, 256>>>(x, wts, N * CIN);

  const int grid1 = (N + TILE - 1) / TILE;
  producer_kernel<<<grid1, NT>>>(q_pts, s_pts, genW, genB, inds, N, Ns);

  const int grid3 = (N + 127) / 128;
  gemm_kernel<<<grid3, GNT, GSMEM>>>(out, N);
}